// round 14
// baseline (speedup 1.0000x reference)
#include <cuda_runtime.h>
#include <cuda_fp16.h>
#include <math.h>
#include <stdint.h>

// ---------------- problem constants ----------------
#define NL_LAYERS 3
#define N_HEADS   16
#define EMB       1024
#define HEAD_DIM  64
#define SEQ_T     1024
#define BATCH     4
#define ROWS      (BATCH * SEQ_T)      // 4096
#define VOCAB     32000
#define E3        (3 * EMB)            // 3072
#define FF_DIM    (4 * EMB)            // 4096
#define LN_EPS    1e-5f
#define ATT_SCALE 0.03125f             // 1/sqrt(EMB) = 1/32

// ---------------- scratch (device globals; no allocation allowed) ----------------
__device__ float  g_x   [ROWS * EMB];
__device__ __half g_h16 [ROWS * EMB];
__device__ __half g_qkv16[ROWS * E3];
__device__ __half g_att16[ROWS * EMB];
__device__ __half g_ff16[ROWS * FF_DIM];
__device__ __half g_wqkv[NL_LAYERS * E3 * EMB];
__device__ __half g_wo  [NL_LAYERS * EMB * EMB];
__device__ __half g_w1  [NL_LAYERS * FF_DIM * EMB];
__device__ __half g_w2  [NL_LAYERS * EMB * FF_DIM];
__device__ __half g_lmw [(size_t)VOCAB * EMB];
__device__ float  g_logits[(size_t)ROWS * VOCAB];
__device__ float  g_rowloss[ROWS];

// ---------------- async copy ----------------
#define CP_ASYNC16(dst, src)                                                  \
    asm volatile("cp.async.cg.shared.global [%0], [%1], 16;" ::               \
                 "r"(dst), "l"(src))
#define CP_COMMIT() asm volatile("cp.async.commit_group;")
#define CP_WAIT(n)  asm volatile("cp.async.wait_group %0;" :: "n"(n))

#define MMA_F16(d, a, b)                                                      \
    asm volatile("mma.sync.aligned.m16n8k16.row.col.f32.f16.f16.f32 "         \
                 "{%0,%1,%2,%3}, {%4,%5,%6,%7}, {%8,%9}, {%0,%1,%2,%3};"      \
                 : "+f"(d[0]), "+f"(d[1]), "+f"(d[2]), "+f"(d[3])             \
                 : "r"(a[0]), "r"(a[1]), "r"(a[2]), "r"(a[3]),                \
                   "r"(b[0]), "r"(b[1]))

#define LDSM_X4(r0, r1, r2, r3, addr)                                         \
    asm volatile("ldmatrix.sync.aligned.m8n8.x4.shared.b16 {%0,%1,%2,%3}, [%4];" \
                 : "=r"(r0), "=r"(r1), "=r"(r2), "=r"(r3) : "r"(addr))
#define LDSM_X4_T(r0, r1, r2, r3, addr)                                       \
    asm volatile("ldmatrix.sync.aligned.m8n8.x4.trans.shared.b16 {%0,%1,%2,%3}, [%4];" \
                 : "=r"(r0), "=r"(r1), "=r"(r2), "=r"(r3) : "r"(addr))

__device__ __forceinline__ unsigned h2u(float a, float b) {
    __half2 h = __floats2half2_rn(a, b);
    return *(unsigned*)&h;
}

// ---------------- prepack wq/wk/wv -> transposed [l][3E][E] fp16 ----------------
__global__ void prepack_qkv(const float* __restrict__ wq,
                            const float* __restrict__ wk,
                            const float* __restrict__ wv) {
    int idx = blockIdx.x * blockDim.x + threadIdx.x;
    int total = NL_LAYERS * E3 * EMB;
    if (idx >= total) return;
    int l = idx / (E3 * EMB);
    int r = idx % (E3 * EMB);
    int c = r / EMB;
    int e = r % EMB;
    float v;
    if (c < EMB) {
        int h = c >> 6, d = c & 63;
        v = wq[(((size_t)l * N_HEADS + h) * EMB + e) * HEAD_DIM + d];
    } else if (c < 2 * EMB) {
        int c2 = c - EMB; int h = c2 >> 6, d = c2 & 63;
        v = wk[(((size_t)l * N_HEADS + h) * EMB + e) * HEAD_DIM + d];
    } else {
        int c2 = c - 2 * EMB; int h = c2 >> 6, d = c2 & 63;
        v = wv[(((size_t)l * N_HEADS + h) * EMB + e) * HEAD_DIM + d];
    }
    g_wqkv[idx] = __float2half(v);
}

// ---------------- tiled transpose + fp16 cvt: src[R][C] f32 -> dst[C][R] f16 ----
__global__ void transpose_cvt(const float* __restrict__ src, __half* __restrict__ dst,
                              int R, int C) {
    __shared__ float tile[32][33];
    int bx = blockIdx.x * 32;
    int by = blockIdx.y * 32;
    int tx = threadIdx.x, ty = threadIdx.y;   // 32 x 8
    #pragma unroll
    for (int i = 0; i < 32; i += 8)
        tile[ty + i][tx] = src[(size_t)(by + ty + i) * C + bx + tx];
    __syncthreads();
    #pragma unroll
    for (int i = 0; i < 32; i += 8)
        dst[(size_t)(bx + ty + i) * R + by + tx] = __float2half(tile[tx][ty + i]);
}

// ---------------- embedding ----------------
__global__ void embed_kernel(const int* __restrict__ ids,
                             const float* __restrict__ tok_emb,
                             const float* __restrict__ pos_emb) {
    int idx = blockIdx.x * blockDim.x + threadIdx.x;
    if (idx >= ROWS * EMB) return;
    int row = idx >> 10;
    int e   = idx & 1023;
    int t   = row & (SEQ_T - 1);
    int tok = ids[row];
    g_x[idx] = tok_emb[(size_t)tok * EMB + e] + pos_emb[(size_t)t * EMB + e];
}

// ---------------- layernorm (fp16 output) ----------------
__global__ void ln_kernel(const float* __restrict__ in,
                          const float* __restrict__ gamma,
                          const float* __restrict__ beta,
                          __half* __restrict__ out) {
    int row = blockIdx.x;
    int tid = threadIdx.x;                 // 256 threads
    const float* p = in + (size_t)row * EMB;
    float s = 0.f, s2 = 0.f;
    #pragma unroll
    for (int i = 0; i < 4; i++) {
        float v = p[tid + i * 256];
        s += v; s2 += v * v;
    }
    __shared__ float rs[256], rs2[256];
    rs[tid] = s; rs2[tid] = s2;
    __syncthreads();
    for (int st = 128; st > 0; st >>= 1) {
        if (tid < st) { rs[tid] += rs[tid + st]; rs2[tid] += rs2[tid + st]; }
        __syncthreads();
    }
    float mu  = rs[0]  * (1.0f / EMB);
    float var = rs2[0] * (1.0f / EMB) - mu * mu;
    float inv = rsqrtf(var + LN_EPS);
    __half* o = out + (size_t)row * EMB;
    #pragma unroll
    for (int i = 0; i < 4; i++) {
        int e = tid + i * 256;
        o[e] = __float2half((p[e] - mu) * inv * gamma[e] + beta[e]);
    }
}

// ---------------- fp16 tensor-core GEMM 128x128 (LDSM + SW128) ----------------
#define TBM 128
#define TBN 128
#define TBK 64
#define STG_BYTES 16384
#define GEMM_SMEM (4 * STG_BYTES)

__global__ __launch_bounds__(256, 2)
void hgemm(const __half* __restrict__ A, const __half* __restrict__ Bt,
           const float* __restrict__ bias, const float* __restrict__ res,
           float* __restrict__ C, __half* __restrict__ Ch,
           int M, int N, int K, int relu) {
    extern __shared__ char smraw[];
    const unsigned sbase = (unsigned)__cvta_generic_to_shared(smraw);

    const int tid  = threadIdx.x;
    const int lane = tid & 31;
    const int wid  = tid >> 5;
    const int wm   = (wid & 1) * 64;
    const int wn   = (wid >> 1) * 32;
    const int g    = lane >> 2;
    const int tg   = lane & 3;

    const int brow = blockIdx.y * TBM;
    const int bcol = blockIdx.x * TBN;

    const __half* Ag = A  + (size_t)brow * K;
    const __half* Bg = Bt + (size_t)bcol * K;

    const int lrow = tid >> 3;
    const int ljc  = tid & 7;

    const int quad  = lane >> 3;
    const int lr8   = lane & 7;
    const int a_qh  = quad >> 1;
    const int a_rl  = (quad & 1) * 8;
    const int b_ql  = quad & 1;
    const int b_rh  = (quad >> 1) * 8;

    unsigned arow_off[4], arow_x[4], brow_off[2], brow_x[2];
    #pragma unroll
    for (int mt = 0; mt < 4; mt++) {
        int r = wm + mt * 16 + a_rl + lr8;
        arow_off[mt] = r * 128; arow_x[mt] = r & 7;
    }
    #pragma unroll
    for (int p = 0; p < 2; p++) {
        int r = wn + p * 16 + b_rh + lr8;
        brow_off[p] = r * 128; brow_x[p] = r & 7;
    }

    float acc[4][4][4];
    #pragma unroll
    for (int i = 0; i < 4; i++)
        #pragma unroll
        for (int j = 0; j < 4; j++)
            #pragma unroll
            for (int c = 0; c < 4; c++) acc[i][j][c] = 0.f;

    const int KT = K / TBK;

    #define LOAD_STAGE(stg, kt_) do {                                         \
        int k0 = (kt_) * TBK;                                                 \
        unsigned aB = sbase + (stg) * 2 * STG_BYTES;                          \
        unsigned bB = aB + STG_BYTES;                                         \
        _Pragma("unroll")                                                     \
        for (int i = 0; i < 4; i++) {                                         \
            int r = lrow + i * 32;                                            \
            unsigned sw = (unsigned)((ljc ^ (r & 7)) << 4) + r * 128;         \
            CP_ASYNC16(aB + sw, Ag + (size_t)r * K + k0 + ljc * 8);           \
            CP_ASYNC16(bB + sw, Bg + (size_t)r * K + k0 + ljc * 8);           \
        }                                                                     \
        CP_COMMIT();                                                          \
    } while (0)

    LOAD_STAGE(0, 0);

    for (int kt = 0; kt < KT; kt++) {
        const int cur = kt & 1;
        if (kt + 1 < KT) {
            LOAD_STAGE(cur ^ 1, kt + 1);
            CP_WAIT(1);
        } else {
            CP_WAIT(0);
        }
        __syncthreads();

        const unsigned aBase = sbase + cur * 2 * STG_BYTES;
        const unsigned bBase = aBase + STG_BYTES;

        #pragma unroll
        for (int ks = 0; ks < 4; ks++) {
            unsigned a_[4][4], b_[4][2];
            #pragma unroll
            for (int mt = 0; mt < 4; mt++) {
                unsigned addr = aBase + arow_off[mt] +
                    ((unsigned)(((2 * ks + a_qh) ^ arow_x[mt])) << 4);
                LDSM_X4(a_[mt][0], a_[mt][1], a_[mt][2], a_[mt][3], addr);
            }
            #pragma unroll
            for (int p = 0; p < 2; p++) {
                unsigned addr = bBase + brow_off[p] +
                    ((unsigned)(((2 * ks + b_ql) ^ brow_x[p])) << 4);
                unsigned r0, r1, r2, r3;
                LDSM_X4(r0, r1, r2, r3, addr);
                b_[2 * p][0] = r0;     b_[2 * p][1] = r1;
                b_[2 * p + 1][0] = r2; b_[2 * p + 1][1] = r3;
            }
            #pragma unroll
            for (int mt = 0; mt < 4; mt++)
                #pragma unroll
                for (int nt = 0; nt < 4; nt++)
                    MMA_F16(acc[mt][nt], a_[mt], b_[nt]);
        }
        __syncthreads();
    }

    #pragma unroll
    for (int mt = 0; mt < 4; mt++) {
        int r0 = brow + wm + mt * 16 + g;
        #pragma unroll
        for (int nt = 0; nt < 4; nt++) {
            int c0 = bcol + wn + nt * 8 + tg * 2;
            float b0 = 0.f, b1 = 0.f;
            if (bias) { b0 = bias[c0]; b1 = bias[c0 + 1]; }
            #pragma unroll
            for (int half_ = 0; half_ < 2; half_++) {
                int r = r0 + half_ * 8;
                float v0 = acc[mt][nt][half_ * 2 + 0] + b0;
                float v1 = acc[mt][nt][half_ * 2 + 1] + b1;
                if (res) {
                    const float2 rr = *(const float2*)(res + (size_t)r * N + c0);
                    v0 += rr.x; v1 += rr.y;
                }
                if (relu) { v0 = fmaxf(v0, 0.f); v1 = fmaxf(v1, 0.f); }
                if (C) {
                    float2 o; o.x = v0; o.y = v1;
                    *(float2*)(C + (size_t)r * N + c0) = o;
                }
                if (Ch) {
                    __half2 oh = __floats2half2_rn(v0, v1);
                    *(__half2*)(Ch + (size_t)r * N + c0) = oh;
                }
            }
        }
    }
}

// ---------------- fp16 tensor-core GEMM 128x256 (wide, for large N) ----------------
// Warp tile 64x64: MMA:LDSM = 32:8 per k-step; B traffic halved.
#define WTBN 256
#define WSTG_A 16384
#define WSTG_B 32768
#define WSTG   (WSTG_A + WSTG_B)
#define GEMMW_SMEM (2 * WSTG)            // 98304 B

__global__ __launch_bounds__(256, 1)
void hgemm_wide(const __half* __restrict__ A, const __half* __restrict__ Bt,
                const float* __restrict__ bias, const float* __restrict__ res,
                float* __restrict__ C, __half* __restrict__ Ch,
                int M, int N, int K, int relu) {
    extern __shared__ char smraw[];
    const unsigned sbase = (unsigned)__cvta_generic_to_shared(smraw);

    const int tid  = threadIdx.x;
    const int lane = tid & 31;
    const int wid  = tid >> 5;
    const int wm   = (wid & 1) * 64;
    const int wn   = (wid >> 1) * 64;      // 4 n-warps x 64
    const int g    = lane >> 2;
    const int tg   = lane & 3;

    const int brow = blockIdx.y * TBM;
    const int bcol = blockIdx.x * WTBN;

    const __half* Ag = A  + (size_t)brow * K;
    const __half* Bg = Bt + (size_t)bcol * K;

    const int lrow = tid >> 3;
    const int ljc  = tid & 7;

    const int quad  = lane >> 3;
    const int lr8   = lane & 7;
    const int a_qh  = quad >> 1;
    const int a_rl  = (quad & 1) * 8;
    const int b_ql  = quad & 1;
    const int b_rh  = (quad >> 1) * 8;

    unsigned arow_off[4], arow_x[4], brow_off[4], brow_x[4];
    #pragma unroll
    for (int mt = 0; mt < 4; mt++) {
        int r = wm + mt * 16 + a_rl + lr8;
        arow_off[mt] = r * 128; arow_x[mt] = r & 7;
    }
    #pragma unroll
    for (int p = 0; p < 4; p++) {
        int r = wn + p * 16 + b_rh + lr8;
        brow_off[p] = r * 128; brow_x[p] = r & 7;
    }

    float acc[4][8][4];
    #pragma unroll
    for (int i = 0; i < 4; i++)
        #pragma unroll
        for (int j = 0; j < 8; j++)
            #pragma unroll
            for (int c = 0; c < 4; c++) acc[i][j][c] = 0.f;

    const int KT = K / TBK;

    #define WLOAD_STAGE(stg, kt_) do {                                        \
        int k0 = (kt_) * TBK;                                                 \
        unsigned aB = sbase + (stg) * WSTG;                                   \
        unsigned bB = aB + WSTG_A;                                            \
        _Pragma("unroll")                                                     \
        for (int i = 0; i < 4; i++) {                                         \
            int r = lrow + i * 32;                                            \
            unsigned sw = (unsigned)((ljc ^ (r & 7)) << 4) + r * 128;         \
            CP_ASYNC16(aB + sw, Ag + (size_t)r * K + k0 + ljc * 8);           \
        }                                                                     \
        _Pragma("unroll")                                                     \
        for (int i = 0; i < 8; i++) {                                         \
            int r = lrow + i * 32;                                            \
            unsigned sw = (unsigned)((ljc ^ (r & 7)) << 4) + r * 128;         \
            CP_ASYNC16(bB + sw, Bg + (size_t)r * K + k0 + ljc * 8);           \
        }                                                                     \
        CP_COMMIT();                                                          \
    } while (0)

    WLOAD_STAGE(0, 0);

    for (int kt = 0; kt < KT; kt++) {
        const int cur = kt & 1;
        if (kt + 1 < KT) {
            WLOAD_STAGE(cur ^ 1, kt + 1);
            CP_WAIT(1);
        } else {
            CP_WAIT(0);
        }
        __syncthreads();

        const unsigned aBase = sbase + cur * WSTG;
        const unsigned bBase = aBase + WSTG_A;

        #pragma unroll
        for (int ks = 0; ks < 4; ks++) {
            unsigned a_[4][4], b_[8][2];
            #pragma unroll
            for (int mt = 0; mt < 4; mt++) {
                unsigned addr = aBase + arow_off[mt] +
                    ((unsigned)(((2 * ks + a_qh) ^ arow_x[mt])) << 4);
                LDSM_X4(a_[mt][0], a_[mt][1], a_[mt][2], a_[mt][3], addr);
            }
            #pragma unroll
            for (int p = 0; p < 4; p++) {
                unsigned addr = bBase + brow_off[p] +
                    ((unsigned)(((2 * ks + b_ql) ^ brow_x[p])) << 4);
                unsigned r0, r1, r2, r3;
                LDSM_X4(r0, r1, r2, r3, addr);
                b_[2 * p][0] = r0;     b_[2 * p][1] = r1;
                b_[2 * p + 1][0] = r2; b_[2 * p + 1][1] = r3;
            }
            #pragma unroll
            for (int mt = 0; mt < 4; mt++)
                #pragma unroll
                for (int nt = 0; nt < 8; nt++)
                    MMA_F16(acc[mt][nt], a_[mt], b_[nt]);
        }
        __syncthreads();
    }

    #pragma unroll
    for (int mt = 0; mt < 4; mt++) {
        int r0 = brow + wm + mt * 16 + g;
        #pragma unroll
        for (int nt = 0; nt < 8; nt++) {
            int c0 = bcol + wn + nt * 8 + tg * 2;
            float b0 = 0.f, b1 = 0.f;
            if (bias) { b0 = bias[c0]; b1 = bias[c0 + 1]; }
            #pragma unroll
            for (int half_ = 0; half_ < 2; half_++) {
                int r = r0 + half_ * 8;
                float v0 = acc[mt][nt][half_ * 2 + 0] + b0;
                float v1 = acc[mt][nt][half_ * 2 + 1] + b1;
                if (res) {
                    const float2 rr = *(const float2*)(res + (size_t)r * N + c0);
                    v0 += rr.x; v1 += rr.y;
                }
                if (relu) { v0 = fmaxf(v0, 0.f); v1 = fmaxf(v1, 0.f); }
                if (C) {
                    float2 o; o.x = v0; o.y = v1;
                    *(float2*)(C + (size_t)r * N + c0) = o;
                }
                if (Ch) {
                    __half2 oh = __floats2half2_rn(v0, v1);
                    *(__half2*)(Ch + (size_t)r * N + c0) = oh;
                }
            }
        }
    }
}

// ---------------- tensor-core flash attention ----------------
#define FA_SMEM (5 * 8192)

__global__ __launch_bounds__(128)
void flash_attn_tc(const __half* __restrict__ qkv, __half* __restrict__ att) {
    extern __shared__ char smraw[];
    const unsigned sbase = (unsigned)__cvta_generic_to_shared(smraw);
    const unsigned sQ = sbase;

    const int qt = blockIdx.x, h = blockIdx.y, b = blockIdx.z;
    const int tid  = threadIdx.x;
    const int lane = tid & 31;
    const int w    = tid >> 5;
    const int g    = lane >> 2;
    const int tg   = lane & 3;
    const int li   = lane >> 3;
    const int lr8  = lane & 7;

    const __half* qbase = qkv + (size_t)(b * SEQ_T) * E3 + h * HEAD_DIM;
    const __half* kbase = qbase + EMB;
    const __half* vbase = qbase + 2 * EMB;

    {
        int r = tid >> 1, c0 = (tid & 1) * 4;
        const __half* src = qbase + (size_t)(qt * 64 + r) * E3;
        #pragma unroll
        for (int i = 0; i < 4; i++) {
            int c = c0 + i;
            CP_ASYNC16(sQ + r * 128 + ((c ^ (r & 7)) << 4), src + c * 8);
        }
        CP_COMMIT();
    }

    #define FA_LOADKV(stg, kt_) do {                                          \
        unsigned kB = sbase + 8192 + (stg) * 16384;                           \
        unsigned vB = kB + 8192;                                              \
        int r = tid >> 1, c0 = (tid & 1) * 4;                                 \
        const __half* ksrc = kbase + (size_t)((kt_) * 64 + r) * E3;           \
        const __half* vsrc = vbase + (size_t)((kt_) * 64 + r) * E3;           \
        _Pragma("unroll")                                                     \
        for (int i = 0; i < 4; i++) {                                         \
            int c = c0 + i;                                                   \
            unsigned swo = r * 128 + ((c ^ (r & 7)) << 4);                    \
            CP_ASYNC16(kB + swo, ksrc + c * 8);                               \
            CP_ASYNC16(vB + swo, vsrc + c * 8);                               \
        }                                                                     \
        CP_COMMIT();                                                          \
    } while (0)

    FA_LOADKV(0, 0);

    float S[8][4], O[8][4];
    float mrow[2] = {-1e30f, -1e30f}, lrow[2] = {0.f, 0.f};
    #pragma unroll
    for (int n = 0; n < 8; n++)
        #pragma unroll
        for (int c = 0; c < 4; c++) O[n][c] = 0.f;
    unsigned Qf[4][4];

    const int qrow0 = qt * 64 + w * 16 + g;

    for (int kt = 0; kt <= qt; kt++) {
        if (kt < qt) { FA_LOADKV((kt + 1) & 1, kt + 1); CP_WAIT(1); }
        else         { CP_WAIT(0); }
        __syncthreads();

        const unsigned kB = sbase + 8192 + (kt & 1) * 16384;
        const unsigned vB = kB + 8192;

        if (kt == 0) {
            #pragma unroll
            for (int q = 0; q < 4; q++) {
                int r = w * 16 + ((li & 1) << 3) + lr8;
                int c = 2 * q + (li >> 1);
                unsigned addr = sQ + r * 128 + ((c ^ (r & 7)) << 4);
                LDSM_X4(Qf[q][0], Qf[q][1], Qf[q][2], Qf[q][3], addr);
            }
        }

        #pragma unroll
        for (int n = 0; n < 8; n++)
            #pragma unroll
            for (int c = 0; c < 4; c++) S[n][c] = 0.f;
        #pragma unroll
        for (int q = 0; q < 4; q++) {
            #pragma unroll
            for (int jp = 0; jp < 4; jp++) {
                int r = 16 * jp + ((li >> 1) << 3) + lr8;
                int c = 2 * q + (li & 1);
                unsigned addr = kB + r * 128 + ((c ^ (r & 7)) << 4);
                unsigned k0, k1, k2, k3;
                LDSM_X4(k0, k1, k2, k3, addr);
                unsigned bb0[2] = {k0, k1}, bb1[2] = {k2, k3};
                MMA_F16(S[2 * jp],     Qf[q], bb0);
                MMA_F16(S[2 * jp + 1], Qf[q], bb1);
            }
        }

        float mloc0 = -1e30f, mloc1 = -1e30f;
        #pragma unroll
        for (int j = 0; j < 8; j++) {
            int scol = kt * 64 + 8 * j + 2 * tg;
            float s0 = S[j][0] * ATT_SCALE, s1 = S[j][1] * ATT_SCALE;
            float s2 = S[j][2] * ATT_SCALE, s3 = S[j][3] * ATT_SCALE;
            if (scol     > qrow0)     s0 = -1e30f;
            if (scol + 1 > qrow0)     s1 = -1e30f;
            if (scol     > qrow0 + 8) s2 = -1e30f;
            if (scol + 1 > qrow0 + 8) s3 = -1e30f;
            S[j][0] = s0; S[j][1] = s1; S[j][2] = s2; S[j][3] = s3;
            mloc0 = fmaxf(mloc0, fmaxf(s0, s1));
            mloc1 = fmaxf(mloc1, fmaxf(s2, s3));
        }
        #pragma unroll
        for (int off = 1; off <= 2; off <<= 1) {
            mloc0 = fmaxf(mloc0, __shfl_xor_sync(0xffffffffu, mloc0, off));
            mloc1 = fmaxf(mloc1, __shfl_xor_sync(0xffffffffu, mloc1, off));
        }
        float mn0 = fmaxf(mrow[0], mloc0), mn1 = fmaxf(mrow[1], mloc1);
        float corr0 = __expf(mrow[0] - mn0), corr1 = __expf(mrow[1] - mn1);
        mrow[0] = mn0; mrow[1] = mn1;

        unsigned Pf[4][4];
        float rs0 = 0.f, rs1 = 0.f;
        #pragma unroll
        for (int j = 0; j < 8; j++) {
            float p0 = __expf(S[j][0] - mn0);
            float p1 = __expf(S[j][1] - mn0);
            float p2 = __expf(S[j][2] - mn1);
            float p3 = __expf(S[j][3] - mn1);
            rs0 += p0 + p1; rs1 += p2 + p3;
            int q = j >> 1, lohi = (j & 1) << 1;
            Pf[q][lohi]     = h2u(p0, p1);
            Pf[q][lohi + 1] = h2u(p2, p3);
        }
        #pragma unroll
        for (int off = 1; off <= 2; off <<= 1) {
            rs0 += __shfl_xor_sync(0xffffffffu, rs0, off);
            rs1 += __shfl_xor_sync(0xffffffffu, rs1, off);
        }
        lrow[0] = lrow[0] * corr0 + rs0;
        lrow[1] = lrow[1] * corr1 + rs1;
        #pragma unroll
        for (int n = 0; n < 8; n++) {
            O[n][0] *= corr0; O[n][1] *= corr0;
            O[n][2] *= corr1; O[n][3] *= corr1;
        }

        #pragma unroll
        for (int q = 0; q < 4; q++) {
            #pragma unroll
            for (int np = 0; np < 4; np++) {
                int r = 16 * q + ((li & 1) << 3) + lr8;
                int c = 2 * np + (li >> 1);
                unsigned addr = vB + r * 128 + ((c ^ (r & 7)) << 4);
                unsigned v0, v1, v2, v3;
                LDSM_X4_T(v0, v1, v2, v3, addr);
                unsigned bb0[2] = {v0, v1}, bb1[2] = {v2, v3};
                MMA_F16(O[2 * np],     Pf[q], bb0);
                MMA_F16(O[2 * np + 1], Pf[q], bb1);
            }
        }
        __syncthreads();
    }

    float inv0 = 1.0f / lrow[0], inv1 = 1.0f / lrow[1];
    __half* obase = att + (size_t)(b * SEQ_T + qt * 64 + w * 16 + g) * EMB +
                    h * HEAD_DIM;
    #pragma unroll
    for (int n = 0; n < 8; n++) {
        int d = 8 * n + 2 * tg;
        __half2 o0 = __floats2half2_rn(O[n][0] * inv0, O[n][1] * inv0);
        __half2 o1 = __floats2half2_rn(O[n][2] * inv1, O[n][3] * inv1);
        *(__half2*)(obase + d) = o0;
        *(__half2*)(obase + (size_t)8 * EMB + d) = o1;
    }
}

// ---------------- loss (single pass, online max/sum) ----------------
__global__ __launch_bounds__(256)
void loss_rows_kernel(const float* __restrict__ logits, const int* __restrict__ tgt) {
    int row = blockIdx.x;
    int tid = threadIdx.x;
    const float4* lp4 = (const float4*)(logits + (size_t)row * VOCAB);
    float m = -1e30f, s = 0.f;
    for (int i = tid; i < VOCAB / 4; i += 256) {
        float4 v = lp4[i];
        float mx = fmaxf(fmaxf(v.x, v.y), fmaxf(v.z, v.w));
        if (mx > m) { s *= __expf(m - mx); m = mx; }
        s += __expf(v.x - m) + __expf(v.y - m) + __expf(v.z - m) + __expf(v.w - m);
    }
    __shared__ float rm[256], rs[256];
    rm[tid] = m; rs[tid] = s;
    __syncthreads();
    for (int st = 128; st > 0; st >>= 1) {
        if (tid < st) {
            float m1 = rm[tid], m2 = rm[tid + st];
            float M = fmaxf(m1, m2);
            rs[tid] = rs[tid] * __expf(m1 - M) + rs[tid + st] * __expf(m2 - M);
            rm[tid] = M;
        }
        __syncthreads();
    }
    if (tid == 0) {
        const float* lp = logits + (size_t)row * VOCAB;
        g_rowloss[row] = -(lp[tgt[row]] - rm[0] - logf(rs[0]));
    }
}

__global__ __launch_bounds__(256)
void loss_final_kernel(float* __restrict__ out_loss) {
    int tid = threadIdx.x;
    __shared__ float red[256];
    float s = 0.f;
    #pragma unroll
    for (int i = 0; i < ROWS / 256; i++) s += g_rowloss[tid + i * 256];
    red[tid] = s; __syncthreads();
    for (int st = 128; st > 0; st >>= 1) {
        if (tid < st) red[tid] += red[tid + st];
        __syncthreads();
    }
    if (tid == 0) out_loss[0] = red[0] * (1.0f / ROWS);
}

// ---------------- launch ----------------
static void run_gemm(const __half* A, const __half* Bt, const float* bias,
                     const float* res, float* C, __half* Ch,
                     int M, int N, int K, int relu) {
    if (N % WTBN == 0 && N >= 2048) {
        dim3 grid(N / WTBN, M / TBM);
        hgemm_wide<<<grid, 256, GEMMW_SMEM>>>(A, Bt, bias, res, C, Ch, M, N, K, relu);
    } else {
        dim3 grid(N / TBN, M / TBM);
        hgemm<<<grid, 256, GEMM_SMEM>>>(A, Bt, bias, res, C, Ch, M, N, K, relu);
    }
}

extern "C" void kernel_launch(void* const* d_in, const int* in_sizes, int n_in,
                              void* d_out, int out_size) {
    const int*   ids     = (const int*)  d_in[0];
    const int*   targets = (const int*)  d_in[1];
    const float* tok_emb = (const float*)d_in[2];
    const float* pos_emb = (const float*)d_in[3];
    const float* wq      = (const float*)d_in[4];
    const float* wk      = (const float*)d_in[5];
    const float* wv      = (const float*)d_in[6];
    const float* wo      = (const float*)d_in[7];
    const float* bo      = (const float*)d_in[8];
    const float* ln1_g   = (const float*)d_in[9];
    const float* ln1_b   = (const float*)d_in[10];
    const float* w1      = (const float*)d_in[11];
    const float* b1      = (const float*)d_in[12];
    const float* w2      = (const float*)d_in[13];
    const float* b2      = (const float*)d_in[14];
    const float* lnf_g   = (const float*)d_in[15];
    const float* lnf_b   = (const float*)d_in[16];
    const float* lm_w    = (const float*)d_in[17];
    const float* lm_b    = (const float*)d_in[18];

    static int attr_set = 0;
    if (!attr_set) {
        cudaFuncSetAttribute(hgemm, cudaFuncAttributeMaxDynamicSharedMemorySize,
                             GEMM_SMEM);
        cudaFuncSetAttribute(hgemm_wide, cudaFuncAttributeMaxDynamicSharedMemorySize,
                             GEMMW_SMEM);
        cudaFuncSetAttribute(flash_attn_tc, cudaFuncAttributeMaxDynamicSharedMemorySize,
                             FA_SMEM);
        attr_set = 1;
    }

    float*  x;    cudaGetSymbolAddress((void**)&x,    g_x);
    __half* h16;  cudaGetSymbolAddress((void**)&h16,  g_h16);
    __half* qkv16;cudaGetSymbolAddress((void**)&qkv16,g_qkv16);
    __half* att16;cudaGetSymbolAddress((void**)&att16,g_att16);
    __half* ff16; cudaGetSymbolAddress((void**)&ff16, g_ff16);
    __half* wqkvp;cudaGetSymbolAddress((void**)&wqkvp,g_wqkv);
    __half* wop;  cudaGetSymbolAddress((void**)&wop,  g_wo);
    __half* w1p;  cudaGetSymbolAddress((void**)&w1p,  g_w1);
    __half* w2p;  cudaGetSymbolAddress((void**)&w2p,  g_w2);
    __half* lmwp; cudaGetSymbolAddress((void**)&lmwp, g_lmw);
    float*  glog; cudaGetSymbolAddress((void**)&glog, g_logits);

    const long long NLOG = (long long)ROWS * VOCAB;
    float* logits = ((long long)out_size >= NLOG) ? (float*)d_out : glog;

    dim3 tb(32, 8);
    dim3 agrid(SEQ_T / 64, N_HEADS, BATCH);

    // Launch order chosen so ncu's "-s 5 -c 1" lands on the first big hgemm:
    // 1 prepack, 2 embed, 3 lmw-cvt, 4 ln0, 5 wo0-cvt, 6 QKV hgemm (wide).
    {
        int total = NL_LAYERS * E3 * EMB;
        prepack_qkv<<<(total + 255) / 256, 256>>>(wq, wk, wv);           // 1
    }
    embed_kernel<<<(ROWS * EMB + 255) / 256, 256>>>(ids, tok_emb, pos_emb); // 2
    transpose_cvt<<<dim3(VOCAB / 32, EMB / 32), tb>>>(lm_w, lmwp, EMB, VOCAB); // 3

    for (int l = 0; l < NL_LAYERS; l++) {
        const float* g1  = ln1_g + l * EMB;
        const float* bt1 = ln1_b + l * EMB;

        // h16 = f16(LN(x))
        ln_kernel<<<ROWS, 256>>>(x, g1, bt1, h16);                       // 4 (l=0)
        // weight cvt for this layer (before each first use)
        transpose_cvt<<<dim3(EMB / 32, EMB / 32), tb>>>(
            wo + (size_t)l * EMB * EMB, wop + (size_t)l * EMB * EMB, EMB, EMB); // 5
        // qkv16 = f16(h @ Wqkv^T)
        run_gemm(h16, wqkvp + (size_t)l * E3 * EMB, nullptr, nullptr, nullptr,
                 qkv16, ROWS, E3, EMB, 0);                               // 6 <- ncu
        transpose_cvt<<<dim3(FF_DIM / 32, EMB / 32), tb>>>(
            w1 + (size_t)l * EMB * FF_DIM, w1p + (size_t)l * EMB * FF_DIM,
            EMB, FF_DIM);
        transpose_cvt<<<dim3(EMB / 32, FF_DIM / 32), tb>>>(
            w2 + (size_t)l * FF_DIM * EMB, w2p + (size_t)l * FF_DIM * EMB,
            FF_DIM, EMB);
        // tensor-core flash attention -> att16
        flash_attn_tc<<<agrid, 128, FA_SMEM>>>(qkv16, att16);
        // x = x + att @ wo + bo
        run_gemm(att16, wop + (size_t)l * EMB * EMB, bo + l * EMB, x, x, nullptr,
                 ROWS, EMB, EMB, 0);
        // h16 = f16(LN(x))
        ln_kernel<<<ROWS, 256>>>(x, g1, bt1, h16);
        // ff16 = f16(relu(h @ w1 + b1))
        run_gemm(h16, w1p + (size_t)l * EMB * FF_DIM, b1 + l * FF_DIM, nullptr,
                 nullptr, ff16, ROWS, FF_DIM, EMB, 1);
        // x = x + ff @ w2 + b2
        run_gemm(ff16, w2p + (size_t)l * FF_DIM * EMB, b2 + l * EMB, x, x, nullptr,
                 ROWS, EMB, FF_DIM, 0);
    }

    // final LN + lm head
    ln_kernel<<<ROWS, 256>>>(x, lnf_g, lnf_b, h16);
    run_gemm(h16, lmwp, lm_b, nullptr, logits, nullptr, ROWS, VOCAB, EMB, 0);

    // loss
    if (out_size == 1 || (long long)out_size > NLOG) {
        loss_rows_kernel<<<ROWS, 256>>>(logits, targets);
        float* loss_dst = (out_size == 1) ? (float*)d_out
                                          : ((float*)d_out + NLOG);
        loss_final_kernel<<<1, 256>>>(loss_dst);
    }
}

// round 16
// speedup vs baseline: 1.0824x; 1.0824x over previous
#include <cuda_runtime.h>
#include <cuda_fp16.h>
#include <math.h>
#include <stdint.h>

// ---------------- problem constants ----------------
#define NL_LAYERS 3
#define N_HEADS   16
#define EMB       1024
#define HEAD_DIM  64
#define SEQ_T     1024
#define BATCH     4
#define ROWS      (BATCH * SEQ_T)      // 4096
#define VOCAB     32000
#define E3        (3 * EMB)            // 3072
#define FF_DIM    (4 * EMB)            // 4096
#define LN_EPS    1e-5f
#define ATT_SCALE 0.03125f             // 1/sqrt(EMB) = 1/32
#define NLTILES   (VOCAB / 128)        // 250 logits column tiles

// ---------------- scratch (device globals; no allocation allowed) ----------------
__device__ float  g_x   [ROWS * EMB];
__device__ __half g_h16 [ROWS * EMB];
__device__ __half g_qkv16[ROWS * E3];
__device__ __half g_att16[ROWS * EMB];
__device__ __half g_ff16[ROWS * FF_DIM];
__device__ __half g_wqkv[NL_LAYERS * E3 * EMB];
__device__ __half g_wo  [NL_LAYERS * EMB * EMB];
__device__ __half g_w1  [NL_LAYERS * FF_DIM * EMB];
__device__ __half g_w2  [NL_LAYERS * EMB * FF_DIM];
__device__ __half g_lmw [(size_t)VOCAB * EMB];
__device__ float  g_logits[(size_t)ROWS * VOCAB];
__device__ float2 g_losspart[(size_t)ROWS * NLTILES];
__device__ float  g_rowloss[ROWS];

// ---------------- async copy ----------------
#define CP_ASYNC16(dst, src)                                                  \
    asm volatile("cp.async.cg.shared.global [%0], [%1], 16;" ::               \
                 "r"(dst), "l"(src))
#define CP_COMMIT() asm volatile("cp.async.commit_group;")
#define CP_WAIT(n)  asm volatile("cp.async.wait_group %0;" :: "n"(n))

#define MMA_F16(d, a, b)                                                      \
    asm volatile("mma.sync.aligned.m16n8k16.row.col.f32.f16.f16.f32 "         \
                 "{%0,%1,%2,%3}, {%4,%5,%6,%7}, {%8,%9}, {%0,%1,%2,%3};"      \
                 : "+f"(d[0]), "+f"(d[1]), "+f"(d[2]), "+f"(d[3])             \
                 : "r"(a[0]), "r"(a[1]), "r"(a[2]), "r"(a[3]),                \
                   "r"(b[0]), "r"(b[1]))

#define LDSM_X4(r0, r1, r2, r3, addr)                                         \
    asm volatile("ldmatrix.sync.aligned.m8n8.x4.shared.b16 {%0,%1,%2,%3}, [%4];" \
                 : "=r"(r0), "=r"(r1), "=r"(r2), "=r"(r3) : "r"(addr))
#define LDSM_X4_T(r0, r1, r2, r3, addr)                                       \
    asm volatile("ldmatrix.sync.aligned.m8n8.x4.trans.shared.b16 {%0,%1,%2,%3}, [%4];" \
                 : "=r"(r0), "=r"(r1), "=r"(r2), "=r"(r3) : "r"(addr))

__device__ __forceinline__ unsigned h2u(float a, float b) {
    __half2 h = __floats2half2_rn(a, b);
    return *(unsigned*)&h;
}

// ---------------- prepack wq/wk/wv -> transposed [l][3E][E] fp16 ----------------
__global__ void prepack_qkv(const float* __restrict__ wq,
                            const float* __restrict__ wk,
                            const float* __restrict__ wv) {
    int idx = blockIdx.x * blockDim.x + threadIdx.x;
    int total = NL_LAYERS * E3 * EMB;
    if (idx >= total) return;
    int l = idx / (E3 * EMB);
    int r = idx % (E3 * EMB);
    int c = r / EMB;
    int e = r % EMB;
    float v;
    if (c < EMB) {
        int h = c >> 6, d = c & 63;
        v = wq[(((size_t)l * N_HEADS + h) * EMB + e) * HEAD_DIM + d];
    } else if (c < 2 * EMB) {
        int c2 = c - EMB; int h = c2 >> 6, d = c2 & 63;
        v = wk[(((size_t)l * N_HEADS + h) * EMB + e) * HEAD_DIM + d];
    } else {
        int c2 = c - 2 * EMB; int h = c2 >> 6, d = c2 & 63;
        v = wv[(((size_t)l * N_HEADS + h) * EMB + e) * HEAD_DIM + d];
    }
    g_wqkv[idx] = __float2half(v);
}

// ---------------- tiled transpose + fp16 cvt: src[R][C] f32 -> dst[C][R] f16 ----
__global__ void transpose_cvt(const float* __restrict__ src, __half* __restrict__ dst,
                              int R, int C) {
    __shared__ float tile[32][33];
    int bx = blockIdx.x * 32;
    int by = blockIdx.y * 32;
    int tx = threadIdx.x, ty = threadIdx.y;   // 32 x 8
    #pragma unroll
    for (int i = 0; i < 32; i += 8)
        tile[ty + i][tx] = src[(size_t)(by + ty + i) * C + bx + tx];
    __syncthreads();
    #pragma unroll
    for (int i = 0; i < 32; i += 8)
        dst[(size_t)(bx + ty + i) * R + by + tx] = __float2half(tile[tx][ty + i]);
}

// ---------------- embedding ----------------
__global__ void embed_kernel(const int* __restrict__ ids,
                             const float* __restrict__ tok_emb,
                             const float* __restrict__ pos_emb) {
    int idx = blockIdx.x * blockDim.x + threadIdx.x;
    if (idx >= ROWS * EMB) return;
    int row = idx >> 10;
    int e   = idx & 1023;
    int t   = row & (SEQ_T - 1);
    int tok = ids[row];
    g_x[idx] = tok_emb[(size_t)tok * EMB + e] + pos_emb[(size_t)t * EMB + e];
}

// ---------------- layernorm (float4, fp16 output) ----------------
__global__ void ln_kernel(const float* __restrict__ in,
                          const float* __restrict__ gamma,
                          const float* __restrict__ beta,
                          __half* __restrict__ out) {
    int row = blockIdx.x;
    int tid = threadIdx.x;                 // 256 threads, 4 floats each
    const float4 v = ((const float4*)(in + (size_t)row * EMB))[tid];
    float s  = v.x + v.y + v.z + v.w;
    float s2 = v.x * v.x + v.y * v.y + v.z * v.z + v.w * v.w;
    __shared__ float rs[256], rs2[256];
    rs[tid] = s; rs2[tid] = s2;
    __syncthreads();
    for (int st = 128; st > 0; st >>= 1) {
        if (tid < st) { rs[tid] += rs[tid + st]; rs2[tid] += rs2[tid + st]; }
        __syncthreads();
    }
    float mu  = rs[0]  * (1.0f / EMB);
    float var = rs2[0] * (1.0f / EMB) - mu * mu;
    float inv = rsqrtf(var + LN_EPS);
    const float4 gm = ((const float4*)gamma)[tid];
    const float4 bt = ((const float4*)beta)[tid];
    __half2 o0 = __floats2half2_rn((v.x - mu) * inv * gm.x + bt.x,
                                   (v.y - mu) * inv * gm.y + bt.y);
    __half2 o1 = __floats2half2_rn((v.z - mu) * inv * gm.z + bt.z,
                                   (v.w - mu) * inv * gm.w + bt.w);
    __half2* o = (__half2*)(out + (size_t)row * EMB);
    o[tid * 2]     = o0;
    o[tid * 2 + 1] = o1;
}

// ---------------- fp16 tensor-core GEMM 128x128 (LDSM + SW128) ----------------
// Optional loss_part: per-row (max, sumexp) partials over this CTA's 128-col tile
// (used by the lm_head GEMM so the loss never re-reads the 524MB logits).
#define TBM 128
#define TBN 128
#define TBK 64
#define STG_BYTES 16384
#define GEMM_SMEM (4 * STG_BYTES)

__global__ __launch_bounds__(256, 2)
void hgemm(const __half* __restrict__ A, const __half* __restrict__ Bt,
           const float* __restrict__ bias, const float* __restrict__ res,
           float* __restrict__ C, __half* __restrict__ Ch,
           float2* __restrict__ loss_part,
           int M, int N, int K, int relu) {
    extern __shared__ char smraw[];
    const unsigned sbase = (unsigned)__cvta_generic_to_shared(smraw);

    const int tid  = threadIdx.x;
    const int lane = tid & 31;
    const int wid  = tid >> 5;
    const int wm   = (wid & 1) * 64;
    const int wn   = (wid >> 1) * 32;
    const int g    = lane >> 2;
    const int tg   = lane & 3;

    const int brow = blockIdx.y * TBM;
    const int bcol = blockIdx.x * TBN;

    const __half* Ag = A  + (size_t)brow * K;
    const __half* Bg = Bt + (size_t)bcol * K;

    const int lrow = tid >> 3;
    const int ljc  = tid & 7;

    const int quad  = lane >> 3;
    const int lr8   = lane & 7;
    const int a_qh  = quad >> 1;
    const int a_rl  = (quad & 1) * 8;
    const int b_ql  = quad & 1;
    const int b_rh  = (quad >> 1) * 8;

    unsigned arow_off[4], arow_x[4], brow_off[2], brow_x[2];
    #pragma unroll
    for (int mt = 0; mt < 4; mt++) {
        int r = wm + mt * 16 + a_rl + lr8;
        arow_off[mt] = r * 128; arow_x[mt] = r & 7;
    }
    #pragma unroll
    for (int p = 0; p < 2; p++) {
        int r = wn + p * 16 + b_rh + lr8;
        brow_off[p] = r * 128; brow_x[p] = r & 7;
    }

    float acc[4][4][4];
    #pragma unroll
    for (int i = 0; i < 4; i++)
        #pragma unroll
        for (int j = 0; j < 4; j++)
            #pragma unroll
            for (int c = 0; c < 4; c++) acc[i][j][c] = 0.f;

    const int KT = K / TBK;

    #define LOAD_STAGE(stg, kt_) do {                                         \
        int k0 = (kt_) * TBK;                                                 \
        unsigned aB = sbase + (stg) * 2 * STG_BYTES;                          \
        unsigned bB = aB + STG_BYTES;                                         \
        _Pragma("unroll")                                                     \
        for (int i = 0; i < 4; i++) {                                         \
            int r = lrow + i * 32;                                            \
            unsigned sw = (unsigned)((ljc ^ (r & 7)) << 4) + r * 128;         \
            CP_ASYNC16(aB + sw, Ag + (size_t)r * K + k0 + ljc * 8);           \
            CP_ASYNC16(bB + sw, Bg + (size_t)r * K + k0 + ljc * 8);           \
        }                                                                     \
        CP_COMMIT();                                                          \
    } while (0)

    LOAD_STAGE(0, 0);

    for (int kt = 0; kt < KT; kt++) {
        const int cur = kt & 1;
        if (kt + 1 < KT) {
            LOAD_STAGE(cur ^ 1, kt + 1);
            CP_WAIT(1);
        } else {
            CP_WAIT(0);
        }
        __syncthreads();

        const unsigned aBase = sbase + cur * 2 * STG_BYTES;
        const unsigned bBase = aBase + STG_BYTES;

        #pragma unroll
        for (int ks = 0; ks < 4; ks++) {
            unsigned a_[4][4], b_[4][2];
            #pragma unroll
            for (int mt = 0; mt < 4; mt++) {
                unsigned addr = aBase + arow_off[mt] +
                    ((unsigned)(((2 * ks + a_qh) ^ arow_x[mt])) << 4);
                LDSM_X4(a_[mt][0], a_[mt][1], a_[mt][2], a_[mt][3], addr);
            }
            #pragma unroll
            for (int p = 0; p < 2; p++) {
                unsigned addr = bBase + brow_off[p] +
                    ((unsigned)(((2 * ks + b_ql) ^ brow_x[p])) << 4);
                unsigned r0, r1, r2, r3;
                LDSM_X4(r0, r1, r2, r3, addr);
                b_[2 * p][0] = r0;     b_[2 * p][1] = r1;
                b_[2 * p + 1][0] = r2; b_[2 * p + 1][1] = r3;
            }
            #pragma unroll
            for (int mt = 0; mt < 4; mt++)
                #pragma unroll
                for (int nt = 0; nt < 4; nt++)
                    MMA_F16(acc[mt][nt], a_[mt], b_[nt]);
        }
        __syncthreads();
    }

    // epilogue: store
    #pragma unroll
    for (int mt = 0; mt < 4; mt++) {
        int r0 = brow + wm + mt * 16 + g;
        #pragma unroll
        for (int nt = 0; nt < 4; nt++) {
            int c0 = bcol + wn + nt * 8 + tg * 2;
            float b0 = 0.f, b1 = 0.f;
            if (bias) { b0 = bias[c0]; b1 = bias[c0 + 1]; }
            #pragma unroll
            for (int half_ = 0; half_ < 2; half_++) {
                int r = r0 + half_ * 8;
                float v0 = acc[mt][nt][half_ * 2 + 0] + b0;
                float v1 = acc[mt][nt][half_ * 2 + 1] + b1;
                if (res) {
                    const float2 rr = *(const float2*)(res + (size_t)r * N + c0);
                    v0 += rr.x; v1 += rr.y;
                }
                if (relu) { v0 = fmaxf(v0, 0.f); v1 = fmaxf(v1, 0.f); }
                if (C) {
                    float2 o; o.x = v0; o.y = v1;
                    *(float2*)(C + (size_t)r * N + c0) = o;
                }
                if (Ch) {
                    __half2 oh = __floats2half2_rn(v0, v1);
                    *(__half2*)(Ch + (size_t)r * N + c0) = oh;
                }
            }
        }
    }

    // epilogue: per-row loss partials (lm_head only; assumes res==0, relu==0)
    if (loss_part) {
        __syncthreads();                       // stage smem now reusable
        float* sm_m = (float*)smraw;           // [128][4]
        float* sm_s = sm_m + 512;
        #pragma unroll
        for (int mt = 0; mt < 4; mt++) {
            #pragma unroll
            for (int half_ = 0; half_ < 2; half_++) {
                int rl = wm + mt * 16 + g + half_ * 8;
                float vv[8];
                float mloc = -1e30f;
                #pragma unroll
                for (int nt = 0; nt < 4; nt++) {
                    int c0 = bcol + wn + nt * 8 + tg * 2;
                    float b0 = bias ? bias[c0] : 0.f;
                    float b1 = bias ? bias[c0 + 1] : 0.f;
                    vv[nt * 2]     = acc[mt][nt][half_ * 2 + 0] + b0;
                    vv[nt * 2 + 1] = acc[mt][nt][half_ * 2 + 1] + b1;
                    mloc = fmaxf(mloc, fmaxf(vv[nt * 2], vv[nt * 2 + 1]));
                }
                mloc = fmaxf(mloc, __shfl_xor_sync(0xffffffffu, mloc, 1));
                mloc = fmaxf(mloc, __shfl_xor_sync(0xffffffffu, mloc, 2));
                float sloc = 0.f;
                #pragma unroll
                for (int j = 0; j < 8; j++) sloc += __expf(vv[j] - mloc);
                sloc += __shfl_xor_sync(0xffffffffu, sloc, 1);
                sloc += __shfl_xor_sync(0xffffffffu, sloc, 2);
                if (tg == 0) {
                    sm_m[rl * 4 + (wid >> 1)] = mloc;
                    sm_s[rl * 4 + (wid >> 1)] = sloc;
                }
            }
        }
        __syncthreads();
        if (tid < 128) {
            float Mv = -1e30f;
            #pragma unroll
            for (int j = 0; j < 4; j++) Mv = fmaxf(Mv, sm_m[tid * 4 + j]);
            float Sv = 0.f;
            #pragma unroll
            for (int j = 0; j < 4; j++)
                Sv += sm_s[tid * 4 + j] * __expf(sm_m[tid * 4 + j] - Mv);
            float2 o; o.x = Mv; o.y = Sv;
            loss_part[(size_t)(brow + tid) * gridDim.x + blockIdx.x] = o;
        }
    }
}

// ---------------- tensor-core flash attention ----------------
#define FA_SMEM (5 * 8192)

__global__ __launch_bounds__(128)
void flash_attn_tc(const __half* __restrict__ qkv, __half* __restrict__ att) {
    extern __shared__ char smraw[];
    const unsigned sbase = (unsigned)__cvta_generic_to_shared(smraw);
    const unsigned sQ = sbase;

    const int qt = blockIdx.x, h = blockIdx.y, b = blockIdx.z;
    const int tid  = threadIdx.x;
    const int lane = tid & 31;
    const int w    = tid >> 5;
    const int g    = lane >> 2;
    const int tg   = lane & 3;
    const int li   = lane >> 3;
    const int lr8  = lane & 7;

    const __half* qbase = qkv + (size_t)(b * SEQ_T) * E3 + h * HEAD_DIM;
    const __half* kbase = qbase + EMB;
    const __half* vbase = qbase + 2 * EMB;

    {
        int r = tid >> 1, c0 = (tid & 1) * 4;
        const __half* src = qbase + (size_t)(qt * 64 + r) * E3;
        #pragma unroll
        for (int i = 0; i < 4; i++) {
            int c = c0 + i;
            CP_ASYNC16(sQ + r * 128 + ((c ^ (r & 7)) << 4), src + c * 8);
        }
        CP_COMMIT();
    }

    #define FA_LOADKV(stg, kt_) do {                                          \
        unsigned kB = sbase + 8192 + (stg) * 16384;                           \
        unsigned vB = kB + 8192;                                              \
        int r = tid >> 1, c0 = (tid & 1) * 4;                                 \
        const __half* ksrc = kbase + (size_t)((kt_) * 64 + r) * E3;           \
        const __half* vsrc = vbase + (size_t)((kt_) * 64 + r) * E3;           \
        _Pragma("unroll")                                                     \
        for (int i = 0; i < 4; i++) {                                         \
            int c = c0 + i;                                                   \
            unsigned swo = r * 128 + ((c ^ (r & 7)) << 4);                    \
            CP_ASYNC16(kB + swo, ksrc + c * 8);                               \
            CP_ASYNC16(vB + swo, vsrc + c * 8);                               \
        }                                                                     \
        CP_COMMIT();                                                          \
    } while (0)

    FA_LOADKV(0, 0);

    float S[8][4], O[8][4];
    float mrow[2] = {-1e30f, -1e30f}, lrow[2] = {0.f, 0.f};
    #pragma unroll
    for (int n = 0; n < 8; n++)
        #pragma unroll
        for (int c = 0; c < 4; c++) O[n][c] = 0.f;
    unsigned Qf[4][4];

    const int qrow0 = qt * 64 + w * 16 + g;

    for (int kt = 0; kt <= qt; kt++) {
        if (kt < qt) { FA_LOADKV((kt + 1) & 1, kt + 1); CP_WAIT(1); }
        else         { CP_WAIT(0); }
        __syncthreads();

        const unsigned kB = sbase + 8192 + (kt & 1) * 16384;
        const unsigned vB = kB + 8192;

        if (kt == 0) {
            #pragma unroll
            for (int q = 0; q < 4; q++) {
                int r = w * 16 + ((li & 1) << 3) + lr8;
                int c = 2 * q + (li >> 1);
                unsigned addr = sQ + r * 128 + ((c ^ (r & 7)) << 4);
                LDSM_X4(Qf[q][0], Qf[q][1], Qf[q][2], Qf[q][3], addr);
            }
        }

        #pragma unroll
        for (int n = 0; n < 8; n++)
            #pragma unroll
            for (int c = 0; c < 4; c++) S[n][c] = 0.f;
        #pragma unroll
        for (int q = 0; q < 4; q++) {
            #pragma unroll
            for (int jp = 0; jp < 4; jp++) {
                int r = 16 * jp + ((li >> 1) << 3) + lr8;
                int c = 2 * q + (li & 1);
                unsigned addr = kB + r * 128 + ((c ^ (r & 7)) << 4);
                unsigned k0, k1, k2, k3;
                LDSM_X4(k0, k1, k2, k3, addr);
                unsigned bb0[2] = {k0, k1}, bb1[2] = {k2, k3};
                MMA_F16(S[2 * jp],     Qf[q], bb0);
                MMA_F16(S[2 * jp + 1], Qf[q], bb1);
            }
        }

        float mloc0 = -1e30f, mloc1 = -1e30f;
        #pragma unroll
        for (int j = 0; j < 8; j++) {
            int scol = kt * 64 + 8 * j + 2 * tg;
            float s0 = S[j][0] * ATT_SCALE, s1 = S[j][1] * ATT_SCALE;
            float s2 = S[j][2] * ATT_SCALE, s3 = S[j][3] * ATT_SCALE;
            if (scol     > qrow0)     s0 = -1e30f;
            if (scol + 1 > qrow0)     s1 = -1e30f;
            if (scol     > qrow0 + 8) s2 = -1e30f;
            if (scol + 1 > qrow0 + 8) s3 = -1e30f;
            S[j][0] = s0; S[j][1] = s1; S[j][2] = s2; S[j][3] = s3;
            mloc0 = fmaxf(mloc0, fmaxf(s0, s1));
            mloc1 = fmaxf(mloc1, fmaxf(s2, s3));
        }
        #pragma unroll
        for (int off = 1; off <= 2; off <<= 1) {
            mloc0 = fmaxf(mloc0, __shfl_xor_sync(0xffffffffu, mloc0, off));
            mloc1 = fmaxf(mloc1, __shfl_xor_sync(0xffffffffu, mloc1, off));
        }
        float mn0 = fmaxf(mrow[0], mloc0), mn1 = fmaxf(mrow[1], mloc1);
        float corr0 = __expf(mrow[0] - mn0), corr1 = __expf(mrow[1] - mn1);
        mrow[0] = mn0; mrow[1] = mn1;

        unsigned Pf[4][4];
        float rs0 = 0.f, rs1 = 0.f;
        #pragma unroll
        for (int j = 0; j < 8; j++) {
            float p0 = __expf(S[j][0] - mn0);
            float p1 = __expf(S[j][1] - mn0);
            float p2 = __expf(S[j][2] - mn1);
            float p3 = __expf(S[j][3] - mn1);
            rs0 += p0 + p1; rs1 += p2 + p3;
            int q = j >> 1, lohi = (j & 1) << 1;
            Pf[q][lohi]     = h2u(p0, p1);
            Pf[q][lohi + 1] = h2u(p2, p3);
        }
        #pragma unroll
        for (int off = 1; off <= 2; off <<= 1) {
            rs0 += __shfl_xor_sync(0xffffffffu, rs0, off);
            rs1 += __shfl_xor_sync(0xffffffffu, rs1, off);
        }
        lrow[0] = lrow[0] * corr0 + rs0;
        lrow[1] = lrow[1] * corr1 + rs1;
        #pragma unroll
        for (int n = 0; n < 8; n++) {
            O[n][0] *= corr0; O[n][1] *= corr0;
            O[n][2] *= corr1; O[n][3] *= corr1;
        }

        #pragma unroll
        for (int q = 0; q < 4; q++) {
            #pragma unroll
            for (int np = 0; np < 4; np++) {
                int r = 16 * q + ((li & 1) << 3) + lr8;
                int c = 2 * np + (li >> 1);
                unsigned addr = vB + r * 128 + ((c ^ (r & 7)) << 4);
                unsigned v0, v1, v2, v3;
                LDSM_X4_T(v0, v1, v2, v3, addr);
                unsigned bb0[2] = {v0, v1}, bb1[2] = {v2, v3};
                MMA_F16(O[2 * np],     Pf[q], bb0);
                MMA_F16(O[2 * np + 1], Pf[q], bb1);
            }
        }
        __syncthreads();
    }

    float inv0 = 1.0f / lrow[0], inv1 = 1.0f / lrow[1];
    __half* obase = att + (size_t)(b * SEQ_T + qt * 64 + w * 16 + g) * EMB +
                    h * HEAD_DIM;
    #pragma unroll
    for (int n = 0; n < 8; n++) {
        int d = 8 * n + 2 * tg;
        __half2 o0 = __floats2half2_rn(O[n][0] * inv0, O[n][1] * inv0);
        __half2 o1 = __floats2half2_rn(O[n][2] * inv1, O[n][3] * inv1);
        *(__half2*)(obase + d) = o0;
        *(__half2*)(obase + (size_t)8 * EMB + d) = o1;
    }
}

// ---------------- loss from GEMM partials ----------------
__global__ __launch_bounds__(256)
void loss_rows_kernel(const float* __restrict__ logits, const int* __restrict__ tgt,
                      const float2* __restrict__ part) {
    int row = blockIdx.x;
    int tid = threadIdx.x;
    float m = -1e30f, s = 0.f;
    for (int i = tid; i < NLTILES; i += 256) {
        float2 p = part[(size_t)row * NLTILES + i];
        float M = fmaxf(m, p.x);
        s = s * __expf(m - M) + p.y * __expf(p.x - M);
        m = M;
    }
    __shared__ float rm[256], rs[256];
    rm[tid] = m; rs[tid] = s;
    __syncthreads();
    for (int st = 128; st > 0; st >>= 1) {
        if (tid < st) {
            float m1 = rm[tid], m2 = rm[tid + st];
            float M = fmaxf(m1, m2);
            rs[tid] = rs[tid] * __expf(m1 - M) + rs[tid + st] * __expf(m2 - M);
            rm[tid] = M;
        }
        __syncthreads();
    }
    if (tid == 0) {
        float tv = logits[(size_t)row * VOCAB + tgt[row]];
        g_rowloss[row] = -(tv - rm[0] - logf(rs[0]));
    }
}

__global__ __launch_bounds__(256)
void loss_final_kernel(float* __restrict__ out_loss) {
    int tid = threadIdx.x;
    __shared__ float red[256];
    float s = 0.f;
    #pragma unroll
    for (int i = 0; i < ROWS / 256; i++) s += g_rowloss[tid + i * 256];
    red[tid] = s; __syncthreads();
    for (int st = 128; st > 0; st >>= 1) {
        if (tid < st) red[tid] += red[tid + st];
        __syncthreads();
    }
    if (tid == 0) out_loss[0] = red[0] * (1.0f / ROWS);
}

// ---------------- launch ----------------
static void run_gemm(const __half* A, const __half* Bt, const float* bias,
                     const float* res, float* C, __half* Ch, float2* lossp,
                     int M, int N, int K, int relu) {
    dim3 grid(N / TBN, M / TBM);
    hgemm<<<grid, 256, GEMM_SMEM>>>(A, Bt, bias, res, C, Ch, lossp, M, N, K, relu);
}

extern "C" void kernel_launch(void* const* d_in, const int* in_sizes, int n_in,
                              void* d_out, int out_size) {
    const int*   ids     = (const int*)  d_in[0];
    const int*   targets = (const int*)  d_in[1];
    const float* tok_emb = (const float*)d_in[2];
    const float* pos_emb = (const float*)d_in[3];
    const float* wq      = (const float*)d_in[4];
    const float* wk      = (const float*)d_in[5];
    const float* wv      = (const float*)d_in[6];
    const float* wo      = (const float*)d_in[7];
    const float* bo      = (const float*)d_in[8];
    const float* ln1_g   = (const float*)d_in[9];
    const float* ln1_b   = (const float*)d_in[10];
    const float* w1      = (const float*)d_in[11];
    const float* b1      = (const float*)d_in[12];
    const float* w2      = (const float*)d_in[13];
    const float* b2      = (const float*)d_in[14];
    const float* lnf_g   = (const float*)d_in[15];
    const float* lnf_b   = (const float*)d_in[16];
    const float* lm_w    = (const float*)d_in[17];
    const float* lm_b    = (const float*)d_in[18];

    static int attr_set = 0;
    if (!attr_set) {
        cudaFuncSetAttribute(hgemm, cudaFuncAttributeMaxDynamicSharedMemorySize,
                             GEMM_SMEM);
        cudaFuncSetAttribute(flash_attn_tc, cudaFuncAttributeMaxDynamicSharedMemorySize,
                             FA_SMEM);
        attr_set = 1;
    }

    float*  x;    cudaGetSymbolAddress((void**)&x,    g_x);
    __half* h16;  cudaGetSymbolAddress((void**)&h16,  g_h16);
    __half* qkv16;cudaGetSymbolAddress((void**)&qkv16,g_qkv16);
    __half* att16;cudaGetSymbolAddress((void**)&att16,g_att16);
    __half* ff16; cudaGetSymbolAddress((void**)&ff16, g_ff16);
    __half* wqkvp;cudaGetSymbolAddress((void**)&wqkvp,g_wqkv);
    __half* wop;  cudaGetSymbolAddress((void**)&wop,  g_wo);
    __half* w1p;  cudaGetSymbolAddress((void**)&w1p,  g_w1);
    __half* w2p;  cudaGetSymbolAddress((void**)&w2p,  g_w2);
    __half* lmwp; cudaGetSymbolAddress((void**)&lmwp, g_lmw);
    float*  glog; cudaGetSymbolAddress((void**)&glog, g_logits);
    float2* lossp;cudaGetSymbolAddress((void**)&lossp,g_losspart);

    const long long NLOG = (long long)ROWS * VOCAB;
    float* logits = ((long long)out_size >= NLOG) ? (float*)d_out : glog;

    dim3 tb(32, 8);
    dim3 agrid(SEQ_T / 64, N_HEADS, BATCH);

    // Launch order keeps the 6th launch = first big QKV hgemm (ncu -s 5 -c 1).
    {
        int total = NL_LAYERS * E3 * EMB;
        prepack_qkv<<<(total + 255) / 256, 256>>>(wq, wk, wv);              // 1
    }
    embed_kernel<<<(ROWS * EMB + 255) / 256, 256>>>(ids, tok_emb, pos_emb); // 2
    transpose_cvt<<<dim3(VOCAB / 32, EMB / 32), tb>>>(lm_w, lmwp, EMB, VOCAB); // 3

    for (int l = 0; l < NL_LAYERS; l++) {
        const float* g1  = ln1_g + l * EMB;
        const float* bt1 = ln1_b + l * EMB;

        ln_kernel<<<ROWS, 256>>>(x, g1, bt1, h16);                          // 4 (l=0)
        transpose_cvt<<<dim3(EMB / 32, EMB / 32), tb>>>(
            wo + (size_t)l * EMB * EMB, wop + (size_t)l * EMB * EMB, EMB, EMB); // 5
        // qkv16 = f16(h @ Wqkv^T)
        run_gemm(h16, wqkvp + (size_t)l * E3 * EMB, nullptr, nullptr, nullptr,
                 qkv16, nullptr, ROWS, E3, EMB, 0);                         // 6
        transpose_cvt<<<dim3(FF_DIM / 32, EMB / 32), tb>>>(
            w1 + (size_t)l * EMB * FF_DIM, w1p + (size_t)l * EMB * FF_DIM,
            EMB, FF_DIM);
        transpose_cvt<<<dim3(EMB / 32, FF_DIM / 32), tb>>>(
            w2 + (size_t)l * FF_DIM * EMB, w2p + (size_t)l * FF_DIM * EMB,
            FF_DIM, EMB);
        // tensor-core flash attention -> att16
        flash_attn_tc<<<agrid, 128, FA_SMEM>>>(qkv16, att16);
        // x = x + att @ wo + bo
        run_gemm(att16, wop + (size_t)l * EMB * EMB, bo + l * EMB, x, x, nullptr,
                 nullptr, ROWS, EMB, EMB, 0);
        // h16 = f16(LN(x))
        ln_kernel<<<ROWS, 256>>>(x, g1, bt1, h16);
        // ff16 = f16(relu(h @ w1 + b1))
        run_gemm(h16, w1p + (size_t)l * EMB * FF_DIM, b1 + l * FF_DIM, nullptr,
                 nullptr, ff16, nullptr, ROWS, FF_DIM, EMB, 1);
        // x = x + ff @ w2 + b2
        run_gemm(ff16, w2p + (size_t)l * FF_DIM * EMB, b2 + l * EMB, x, x, nullptr,
                 nullptr, ROWS, EMB, FF_DIM, 0);
    }

    // final LN + lm head (with fused loss partials)
    ln_kernel<<<ROWS, 256>>>(x, lnf_g, lnf_b, h16);
    run_gemm(h16, lmwp, lm_b, nullptr, logits, nullptr, lossp,
             ROWS, VOCAB, EMB, 0);

    // loss from partials
    if (out_size == 1 || (long long)out_size > NLOG) {
        loss_rows_kernel<<<ROWS, 256>>>(logits, targets, lossp);
        float* loss_dst = (out_size == 1) ? (float*)d_out
                                          : ((float*)d_out + NLOG);
        loss_final_kernel<<<1, 256>>>(loss_dst);
    }
}

// round 17
// speedup vs baseline: 1.1286x; 1.0427x over previous
#include <cuda_runtime.h>
#include <cuda_fp16.h>
#include <math.h>
#include <stdint.h>

// ---------------- problem constants ----------------
#define NL_LAYERS 3
#define N_HEADS   16
#define EMB       1024
#define HEAD_DIM  64
#define SEQ_T     1024
#define BATCH     4
#define ROWS      (BATCH * SEQ_T)      // 4096
#define VOCAB     32000
#define E3        (3 * EMB)            // 3072
#define FF_DIM    (4 * EMB)            // 4096
#define LN_EPS    1e-5f
#define ATT_SCALE 0.03125f             // 1/sqrt(EMB) = 1/32
#define NLTILES   (VOCAB / 128)        // 250 logits column tiles

// ---------------- scratch (device globals; no allocation allowed) ----------------
__device__ float  g_x   [ROWS * EMB];
__device__ __half g_h16 [ROWS * EMB];
__device__ __half g_qkv16[ROWS * E3];
__device__ __half g_att16[ROWS * EMB];
__device__ __half g_ff16[ROWS * FF_DIM];
__device__ __half g_wqkv[NL_LAYERS * E3 * EMB];
__device__ __half g_wo  [NL_LAYERS * EMB * EMB];
__device__ __half g_w1  [NL_LAYERS * FF_DIM * EMB];
__device__ __half g_w2  [NL_LAYERS * EMB * FF_DIM];
__device__ __half g_lmw [(size_t)VOCAB * EMB];
__device__ float  g_logits[(size_t)ROWS * VOCAB];
__device__ float2 g_losspart[(size_t)ROWS * NLTILES];
__device__ float  g_rowloss[ROWS];

// ---------------- async copy ----------------
#define CP_ASYNC16(dst, src)                                                  \
    asm volatile("cp.async.cg.shared.global [%0], [%1], 16;" ::               \
                 "r"(dst), "l"(src))
#define CP_COMMIT() asm volatile("cp.async.commit_group;")
#define CP_WAIT(n)  asm volatile("cp.async.wait_group %0;" :: "n"(n))

#define MMA_F16(d, a, b)                                                      \
    asm volatile("mma.sync.aligned.m16n8k16.row.col.f32.f16.f16.f32 "         \
                 "{%0,%1,%2,%3}, {%4,%5,%6,%7}, {%8,%9}, {%0,%1,%2,%3};"      \
                 : "+f"(d[0]), "+f"(d[1]), "+f"(d[2]), "+f"(d[3])             \
                 : "r"(a[0]), "r"(a[1]), "r"(a[2]), "r"(a[3]),                \
                   "r"(b[0]), "r"(b[1]))

#define LDSM_X4(r0, r1, r2, r3, addr)                                         \
    asm volatile("ldmatrix.sync.aligned.m8n8.x4.shared.b16 {%0,%1,%2,%3}, [%4];" \
                 : "=r"(r0), "=r"(r1), "=r"(r2), "=r"(r3) : "r"(addr))
#define LDSM_X4_T(r0, r1, r2, r3, addr)                                       \
    asm volatile("ldmatrix.sync.aligned.m8n8.x4.trans.shared.b16 {%0,%1,%2,%3}, [%4];" \
                 : "=r"(r0), "=r"(r1), "=r"(r2), "=r"(r3) : "r"(addr))

__device__ __forceinline__ unsigned h2u(float a, float b) {
    __half2 h = __floats2half2_rn(a, b);
    return *(unsigned*)&h;
}

// ---------------- prepack wq/wk/wv for ONE layer -> transposed [3E][E] fp16 ----
__global__ void prepack_qkv(const float* __restrict__ wq,
                            const float* __restrict__ wk,
                            const float* __restrict__ wv, int l) {
    int idx = blockIdx.x * blockDim.x + threadIdx.x;
    if (idx >= E3 * EMB) return;
    int c = idx / EMB;
    int e = idx % EMB;
    float v;
    if (c < EMB) {
        int h = c >> 6, d = c & 63;
        v = wq[(((size_t)l * N_HEADS + h) * EMB + e) * HEAD_DIM + d];
    } else if (c < 2 * EMB) {
        int c2 = c - EMB; int h = c2 >> 6, d = c2 & 63;
        v = wk[(((size_t)l * N_HEADS + h) * EMB + e) * HEAD_DIM + d];
    } else {
        int c2 = c - 2 * EMB; int h = c2 >> 6, d = c2 & 63;
        v = wv[(((size_t)l * N_HEADS + h) * EMB + e) * HEAD_DIM + d];
    }
    g_wqkv[(size_t)l * E3 * EMB + idx] = __float2half(v);
}

// ---------------- tiled transpose + fp16 cvt: src[R][C] f32 -> dst[C][R] f16 ----
__global__ void transpose_cvt(const float* __restrict__ src, __half* __restrict__ dst,
                              int R, int C) {
    __shared__ float tile[32][33];
    int bx = blockIdx.x * 32;
    int by = blockIdx.y * 32;
    int tx = threadIdx.x, ty = threadIdx.y;   // 32 x 8
    #pragma unroll
    for (int i = 0; i < 32; i += 8)
        tile[ty + i][tx] = src[(size_t)(by + ty + i) * C + bx + tx];
    __syncthreads();
    #pragma unroll
    for (int i = 0; i < 32; i += 8)
        dst[(size_t)(bx + ty + i) * R + by + tx] = __float2half(tile[tx][ty + i]);
}

// ---------------- embedding (float4) ----------------
__global__ void embed_kernel(const int* __restrict__ ids,
                             const float* __restrict__ tok_emb,
                             const float* __restrict__ pos_emb) {
    int i4 = blockIdx.x * blockDim.x + threadIdx.x;     // < ROWS*256
    if (i4 >= ROWS * (EMB / 4)) return;
    int row = i4 >> 8;
    int c4  = i4 & 255;
    int t   = row & (SEQ_T - 1);
    int tok = ids[row];
    float4 a = ((const float4*)(tok_emb + (size_t)tok * EMB))[c4];
    float4 b = ((const float4*)(pos_emb + (size_t)t * EMB))[c4];
    float4 o; o.x = a.x + b.x; o.y = a.y + b.y; o.z = a.z + b.z; o.w = a.w + b.w;
    ((float4*)g_x)[i4] = o;
}

// ---------------- layernorm (warp-per-row, no block barriers) ----------------
__global__ __launch_bounds__(256)
void ln_kernel(const float* __restrict__ in,
               const float* __restrict__ gamma,
               const float* __restrict__ beta,
               __half* __restrict__ out) {
    const int w    = threadIdx.x >> 5;
    const int lane = threadIdx.x & 31;
    const int row  = blockIdx.x * 8 + w;
    const float4* p = (const float4*)(in + (size_t)row * EMB);
    float4 v[8];
    float s = 0.f, s2 = 0.f;
    #pragma unroll
    for (int i = 0; i < 8; i++) {
        v[i] = p[lane + 32 * i];
        s  += v[i].x + v[i].y + v[i].z + v[i].w;
        s2 += v[i].x * v[i].x + v[i].y * v[i].y + v[i].z * v[i].z + v[i].w * v[i].w;
    }
    #pragma unroll
    for (int off = 16; off > 0; off >>= 1) {
        s  += __shfl_xor_sync(0xffffffffu, s,  off);
        s2 += __shfl_xor_sync(0xffffffffu, s2, off);
    }
    float mu  = s  * (1.0f / EMB);
    float var = s2 * (1.0f / EMB) - mu * mu;
    float inv = rsqrtf(var + LN_EPS);
    const float4* gm4 = (const float4*)gamma;
    const float4* bt4 = (const float4*)beta;
    __half2* o = (__half2*)(out + (size_t)row * EMB);
    #pragma unroll
    for (int i = 0; i < 8; i++) {
        int c = lane + 32 * i;
        float4 gm = gm4[c], bt = bt4[c], vv = v[i];
        o[c * 2]     = __floats2half2_rn((vv.x - mu) * inv * gm.x + bt.x,
                                         (vv.y - mu) * inv * gm.y + bt.y);
        o[c * 2 + 1] = __floats2half2_rn((vv.z - mu) * inv * gm.z + bt.z,
                                         (vv.w - mu) * inv * gm.w + bt.w);
    }
}

// ---------------- fp16 tensor-core GEMM 128x128 (LDSM + SW128) ----------------
#define TBM 128
#define TBN 128
#define TBK 64
#define STG_BYTES 16384
#define GEMM_SMEM (4 * STG_BYTES)

__global__ __launch_bounds__(256, 2)
void hgemm(const __half* __restrict__ A, const __half* __restrict__ Bt,
           const float* __restrict__ bias, const float* __restrict__ res,
           float* __restrict__ C, __half* __restrict__ Ch,
           float2* __restrict__ loss_part,
           int M, int N, int K, int relu) {
    extern __shared__ char smraw[];
    const unsigned sbase = (unsigned)__cvta_generic_to_shared(smraw);

    const int tid  = threadIdx.x;
    const int lane = tid & 31;
    const int wid  = tid >> 5;
    const int wm   = (wid & 1) * 64;
    const int wn   = (wid >> 1) * 32;
    const int g    = lane >> 2;
    const int tg   = lane & 3;

    const int brow = blockIdx.y * TBM;
    const int bcol = blockIdx.x * TBN;

    const __half* Ag = A  + (size_t)brow * K;
    const __half* Bg = Bt + (size_t)bcol * K;

    const int lrow = tid >> 3;
    const int ljc  = tid & 7;

    const int quad  = lane >> 3;
    const int lr8   = lane & 7;
    const int a_qh  = quad >> 1;
    const int a_rl  = (quad & 1) * 8;
    const int b_ql  = quad & 1;
    const int b_rh  = (quad >> 1) * 8;

    unsigned arow_off[4], arow_x[4], brow_off[2], brow_x[2];
    #pragma unroll
    for (int mt = 0; mt < 4; mt++) {
        int r = wm + mt * 16 + a_rl + lr8;
        arow_off[mt] = r * 128; arow_x[mt] = r & 7;
    }
    #pragma unroll
    for (int p = 0; p < 2; p++) {
        int r = wn + p * 16 + b_rh + lr8;
        brow_off[p] = r * 128; brow_x[p] = r & 7;
    }

    float acc[4][4][4];
    #pragma unroll
    for (int i = 0; i < 4; i++)
        #pragma unroll
        for (int j = 0; j < 4; j++)
            #pragma unroll
            for (int c = 0; c < 4; c++) acc[i][j][c] = 0.f;

    const int KT = K / TBK;

    #define LOAD_STAGE(stg, kt_) do {                                         \
        int k0 = (kt_) * TBK;                                                 \
        unsigned aB = sbase + (stg) * 2 * STG_BYTES;                          \
        unsigned bB = aB + STG_BYTES;                                         \
        _Pragma("unroll")                                                     \
        for (int i = 0; i < 4; i++) {                                         \
            int r = lrow + i * 32;                                            \
            unsigned sw = (unsigned)((ljc ^ (r & 7)) << 4) + r * 128;         \
            CP_ASYNC16(aB + sw, Ag + (size_t)r * K + k0 + ljc * 8);           \
            CP_ASYNC16(bB + sw, Bg + (size_t)r * K + k0 + ljc * 8);           \
        }                                                                     \
        CP_COMMIT();                                                          \
    } while (0)

    LOAD_STAGE(0, 0);

    for (int kt = 0; kt < KT; kt++) {
        const int cur = kt & 1;
        if (kt + 1 < KT) {
            LOAD_STAGE(cur ^ 1, kt + 1);
            CP_WAIT(1);
        } else {
            CP_WAIT(0);
        }
        __syncthreads();

        const unsigned aBase = sbase + cur * 2 * STG_BYTES;
        const unsigned bBase = aBase + STG_BYTES;

        #pragma unroll
        for (int ks = 0; ks < 4; ks++) {
            unsigned a_[4][4], b_[4][2];
            #pragma unroll
            for (int mt = 0; mt < 4; mt++) {
                unsigned addr = aBase + arow_off[mt] +
                    ((unsigned)(((2 * ks + a_qh) ^ arow_x[mt])) << 4);
                LDSM_X4(a_[mt][0], a_[mt][1], a_[mt][2], a_[mt][3], addr);
            }
            #pragma unroll
            for (int p = 0; p < 2; p++) {
                unsigned addr = bBase + brow_off[p] +
                    ((unsigned)(((2 * ks + b_ql) ^ brow_x[p])) << 4);
                unsigned r0, r1, r2, r3;
                LDSM_X4(r0, r1, r2, r3, addr);
                b_[2 * p][0] = r0;     b_[2 * p][1] = r1;
                b_[2 * p + 1][0] = r2; b_[2 * p + 1][1] = r3;
            }
            #pragma unroll
            for (int mt = 0; mt < 4; mt++)
                #pragma unroll
                for (int nt = 0; nt < 4; nt++)
                    MMA_F16(acc[mt][nt], a_[mt], b_[nt]);
        }
        __syncthreads();
    }

    // epilogue: store
    #pragma unroll
    for (int mt = 0; mt < 4; mt++) {
        int r0 = brow + wm + mt * 16 + g;
        #pragma unroll
        for (int nt = 0; nt < 4; nt++) {
            int c0 = bcol + wn + nt * 8 + tg * 2;
            float b0 = 0.f, b1 = 0.f;
            if (bias) { b0 = bias[c0]; b1 = bias[c0 + 1]; }
            #pragma unroll
            for (int half_ = 0; half_ < 2; half_++) {
                int r = r0 + half_ * 8;
                float v0 = acc[mt][nt][half_ * 2 + 0] + b0;
                float v1 = acc[mt][nt][half_ * 2 + 1] + b1;
                if (res) {
                    const float2 rr = *(const float2*)(res + (size_t)r * N + c0);
                    v0 += rr.x; v1 += rr.y;
                }
                if (relu) { v0 = fmaxf(v0, 0.f); v1 = fmaxf(v1, 0.f); }
                if (C) {
                    float2 o; o.x = v0; o.y = v1;
                    *(float2*)(C + (size_t)r * N + c0) = o;
                }
                if (Ch) {
                    __half2 oh = __floats2half2_rn(v0, v1);
                    *(__half2*)(Ch + (size_t)r * N + c0) = oh;
                }
            }
        }
    }

    // epilogue: per-row loss partials (lm_head only; assumes res==0, relu==0)
    if (loss_part) {
        __syncthreads();
        float* sm_m = (float*)smraw;           // [128][4]
        float* sm_s = sm_m + 512;
        #pragma unroll
        for (int mt = 0; mt < 4; mt++) {
            #pragma unroll
            for (int half_ = 0; half_ < 2; half_++) {
                int rl = wm + mt * 16 + g + half_ * 8;
                float vv[8];
                float mloc = -1e30f;
                #pragma unroll
                for (int nt = 0; nt < 4; nt++) {
                    int c0 = bcol + wn + nt * 8 + tg * 2;
                    float b0 = bias ? bias[c0] : 0.f;
                    float b1 = bias ? bias[c0 + 1] : 0.f;
                    vv[nt * 2]     = acc[mt][nt][half_ * 2 + 0] + b0;
                    vv[nt * 2 + 1] = acc[mt][nt][half_ * 2 + 1] + b1;
                    mloc = fmaxf(mloc, fmaxf(vv[nt * 2], vv[nt * 2 + 1]));
                }
                mloc = fmaxf(mloc, __shfl_xor_sync(0xffffffffu, mloc, 1));
                mloc = fmaxf(mloc, __shfl_xor_sync(0xffffffffu, mloc, 2));
                float sloc = 0.f;
                #pragma unroll
                for (int j = 0; j < 8; j++) sloc += __expf(vv[j] - mloc);
                sloc += __shfl_xor_sync(0xffffffffu, sloc, 1);
                sloc += __shfl_xor_sync(0xffffffffu, sloc, 2);
                if (tg == 0) {
                    sm_m[rl * 4 + (wid >> 1)] = mloc;
                    sm_s[rl * 4 + (wid >> 1)] = sloc;
                }
            }
        }
        __syncthreads();
        if (tid < 128) {
            float Mv = -1e30f;
            #pragma unroll
            for (int j = 0; j < 4; j++) Mv = fmaxf(Mv, sm_m[tid * 4 + j]);
            float Sv = 0.f;
            #pragma unroll
            for (int j = 0; j < 4; j++)
                Sv += sm_s[tid * 4 + j] * __expf(sm_m[tid * 4 + j] - Mv);
            float2 o; o.x = Mv; o.y = Sv;
            loss_part[(size_t)(brow + tid) * gridDim.x + blockIdx.x] = o;
        }
    }
}

// ---------------- tensor-core flash attention ----------------
#define FA_SMEM (5 * 8192)

__global__ __launch_bounds__(128)
void flash_attn_tc(const __half* __restrict__ qkv, __half* __restrict__ att) {
    extern __shared__ char smraw[];
    const unsigned sbase = (unsigned)__cvta_generic_to_shared(smraw);
    const unsigned sQ = sbase;

    const int qt = blockIdx.x, h = blockIdx.y, b = blockIdx.z;
    const int tid  = threadIdx.x;
    const int lane = tid & 31;
    const int w    = tid >> 5;
    const int g    = lane >> 2;
    const int tg   = lane & 3;
    const int li   = lane >> 3;
    const int lr8  = lane & 7;

    const __half* qbase = qkv + (size_t)(b * SEQ_T) * E3 + h * HEAD_DIM;
    const __half* kbase = qbase + EMB;
    const __half* vbase = qbase + 2 * EMB;

    {
        int r = tid >> 1, c0 = (tid & 1) * 4;
        const __half* src = qbase + (size_t)(qt * 64 + r) * E3;
        #pragma unroll
        for (int i = 0; i < 4; i++) {
            int c = c0 + i;
            CP_ASYNC16(sQ + r * 128 + ((c ^ (r & 7)) << 4), src + c * 8);
        }
        CP_COMMIT();
    }

    #define FA_LOADKV(stg, kt_) do {                                          \
        unsigned kB = sbase + 8192 + (stg) * 16384;                           \
        unsigned vB = kB + 8192;                                              \
        int r = tid >> 1, c0 = (tid & 1) * 4;                                 \
        const __half* ksrc = kbase + (size_t)((kt_) * 64 + r) * E3;           \
        const __half* vsrc = vbase + (size_t)((kt_) * 64 + r) * E3;           \
        _Pragma("unroll")                                                     \
        for (int i = 0; i < 4; i++) {                                         \
            int c = c0 + i;                                                   \
            unsigned swo = r * 128 + ((c ^ (r & 7)) << 4);                    \
            CP_ASYNC16(kB + swo, ksrc + c * 8);                               \
            CP_ASYNC16(vB + swo, vsrc + c * 8);                               \
        }                                                                     \
        CP_COMMIT();                                                          \
    } while (0)

    FA_LOADKV(0, 0);

    float S[8][4], O[8][4];
    float mrow[2] = {-1e30f, -1e30f}, lrow[2] = {0.f, 0.f};
    #pragma unroll
    for (int n = 0; n < 8; n++)
        #pragma unroll
        for (int c = 0; c < 4; c++) O[n][c] = 0.f;
    unsigned Qf[4][4];

    const int qrow0 = qt * 64 + w * 16 + g;

    for (int kt = 0; kt <= qt; kt++) {
        if (kt < qt) { FA_LOADKV((kt + 1) & 1, kt + 1); CP_WAIT(1); }
        else         { CP_WAIT(0); }
        __syncthreads();

        const unsigned kB = sbase + 8192 + (kt & 1) * 16384;
        const unsigned vB = kB + 8192;

        if (kt == 0) {
            #pragma unroll
            for (int q = 0; q < 4; q++) {
                int r = w * 16 + ((li & 1) << 3) + lr8;
                int c = 2 * q + (li >> 1);
                unsigned addr = sQ + r * 128 + ((c ^ (r & 7)) << 4);
                LDSM_X4(Qf[q][0], Qf[q][1], Qf[q][2], Qf[q][3], addr);
            }
        }

        #pragma unroll
        for (int n = 0; n < 8; n++)
            #pragma unroll
            for (int c = 0; c < 4; c++) S[n][c] = 0.f;
        #pragma unroll
        for (int q = 0; q < 4; q++) {
            #pragma unroll
            for (int jp = 0; jp < 4; jp++) {
                int r = 16 * jp + ((li >> 1) << 3) + lr8;
                int c = 2 * q + (li & 1);
                unsigned addr = kB + r * 128 + ((c ^ (r & 7)) << 4);
                unsigned k0, k1, k2, k3;
                LDSM_X4(k0, k1, k2, k3, addr);
                unsigned bb0[2] = {k0, k1}, bb1[2] = {k2, k3};
                MMA_F16(S[2 * jp],     Qf[q], bb0);
                MMA_F16(S[2 * jp + 1], Qf[q], bb1);
            }
        }

        float mloc0 = -1e30f, mloc1 = -1e30f;
        #pragma unroll
        for (int j = 0; j < 8; j++) {
            int scol = kt * 64 + 8 * j + 2 * tg;
            float s0 = S[j][0] * ATT_SCALE, s1 = S[j][1] * ATT_SCALE;
            float s2 = S[j][2] * ATT_SCALE, s3 = S[j][3] * ATT_SCALE;
            if (scol     > qrow0)     s0 = -1e30f;
            if (scol + 1 > qrow0)     s1 = -1e30f;
            if (scol     > qrow0 + 8) s2 = -1e30f;
            if (scol + 1 > qrow0 + 8) s3 = -1e30f;
            S[j][0] = s0; S[j][1] = s1; S[j][2] = s2; S[j][3] = s3;
            mloc0 = fmaxf(mloc0, fmaxf(s0, s1));
            mloc1 = fmaxf(mloc1, fmaxf(s2, s3));
        }
        #pragma unroll
        for (int off = 1; off <= 2; off <<= 1) {
            mloc0 = fmaxf(mloc0, __shfl_xor_sync(0xffffffffu, mloc0, off));
            mloc1 = fmaxf(mloc1, __shfl_xor_sync(0xffffffffu, mloc1, off));
        }
        float mn0 = fmaxf(mrow[0], mloc0), mn1 = fmaxf(mrow[1], mloc1);
        float corr0 = __expf(mrow[0] - mn0), corr1 = __expf(mrow[1] - mn1);
        mrow[0] = mn0; mrow[1] = mn1;

        unsigned Pf[4][4];
        float rs0 = 0.f, rs1 = 0.f;
        #pragma unroll
        for (int j = 0; j < 8; j++) {
            float p0 = __expf(S[j][0] - mn0);
            float p1 = __expf(S[j][1] - mn0);
            float p2 = __expf(S[j][2] - mn1);
            float p3 = __expf(S[j][3] - mn1);
            rs0 += p0 + p1; rs1 += p2 + p3;
            int q = j >> 1, lohi = (j & 1) << 1;
            Pf[q][lohi]     = h2u(p0, p1);
            Pf[q][lohi + 1] = h2u(p2, p3);
        }
        #pragma unroll
        for (int off = 1; off <= 2; off <<= 1) {
            rs0 += __shfl_xor_sync(0xffffffffu, rs0, off);
            rs1 += __shfl_xor_sync(0xffffffffu, rs1, off);
        }
        lrow[0] = lrow[0] * corr0 + rs0;
        lrow[1] = lrow[1] * corr1 + rs1;
        #pragma unroll
        for (int n = 0; n < 8; n++) {
            O[n][0] *= corr0; O[n][1] *= corr0;
            O[n][2] *= corr1; O[n][3] *= corr1;
        }

        #pragma unroll
        for (int q = 0; q < 4; q++) {
            #pragma unroll
            for (int np = 0; np < 4; np++) {
                int r = 16 * q + ((li & 1) << 3) + lr8;
                int c = 2 * np + (li >> 1);
                unsigned addr = vB + r * 128 + ((c ^ (r & 7)) << 4);
                unsigned v0, v1, v2, v3;
                LDSM_X4_T(v0, v1, v2, v3, addr);
                unsigned bb0[2] = {v0, v1}, bb1[2] = {v2, v3};
                MMA_F16(O[2 * np],     Pf[q], bb0);
                MMA_F16(O[2 * np + 1], Pf[q], bb1);
            }
        }
        __syncthreads();
    }

    float inv0 = 1.0f / lrow[0], inv1 = 1.0f / lrow[1];
    __half* obase = att + (size_t)(b * SEQ_T + qt * 64 + w * 16 + g) * EMB +
                    h * HEAD_DIM;
    #pragma unroll
    for (int n = 0; n < 8; n++) {
        int d = 8 * n + 2 * tg;
        __half2 o0 = __floats2half2_rn(O[n][0] * inv0, O[n][1] * inv0);
        __half2 o1 = __floats2half2_rn(O[n][2] * inv1, O[n][3] * inv1);
        *(__half2*)(obase + d) = o0;
        *(__half2*)(obase + (size_t)8 * EMB + d) = o1;
    }
}

// ---------------- loss from GEMM partials ----------------
__global__ __launch_bounds__(256)
void loss_rows_kernel(const float* __restrict__ logits, const int* __restrict__ tgt,
                      const float2* __restrict__ part) {
    int row = blockIdx.x;
    int tid = threadIdx.x;
    float m = -1e30f, s = 0.f;
    for (int i = tid; i < NLTILES; i += 256) {
        float2 p = part[(size_t)row * NLTILES + i];
        float M = fmaxf(m, p.x);
        s = s * __expf(m - M) + p.y * __expf(p.x - M);
        m = M;
    }
    __shared__ float rm[256], rs[256];
    rm[tid] = m; rs[tid] = s;
    __syncthreads();
    for (int st = 128; st > 0; st >>= 1) {
        if (tid < st) {
            float m1 = rm[tid], m2 = rm[tid + st];
            float M = fmaxf(m1, m2);
            rs[tid] = rs[tid] * __expf(m1 - M) + rs[tid + st] * __expf(m2 - M);
            rm[tid] = M;
        }
        __syncthreads();
    }
    if (tid == 0) {
        float tv = logits[(size_t)row * VOCAB + tgt[row]];
        g_rowloss[row] = -(tv - rm[0] - logf(rs[0]));
    }
}

__global__ __launch_bounds__(256)
void loss_final_kernel(float* __restrict__ out_loss) {
    int tid = threadIdx.x;
    __shared__ float red[256];
    float s = 0.f;
    #pragma unroll
    for (int i = 0; i < ROWS / 256; i++) s += g_rowloss[tid + i * 256];
    red[tid] = s; __syncthreads();
    for (int st = 128; st > 0; st >>= 1) {
        if (tid < st) red[tid] += red[tid + st];
        __syncthreads();
    }
    if (tid == 0) out_loss[0] = red[0] * (1.0f / ROWS);
}

// ---------------- launch ----------------
static void run_gemm(const __half* A, const __half* Bt, const float* bias,
                     const float* res, float* C, __half* Ch, float2* lossp,
                     int M, int N, int K, int relu) {
    dim3 grid(N / TBN, M / TBM);
    hgemm<<<grid, 256, GEMM_SMEM>>>(A, Bt, bias, res, C, Ch, lossp, M, N, K, relu);
}

extern "C" void kernel_launch(void* const* d_in, const int* in_sizes, int n_in,
                              void* d_out, int out_size) {
    const int*   ids     = (const int*)  d_in[0];
    const int*   targets = (const int*)  d_in[1];
    const float* tok_emb = (const float*)d_in[2];
    const float* pos_emb = (const float*)d_in[3];
    const float* wq      = (const float*)d_in[4];
    const float* wk      = (const float*)d_in[5];
    const float* wv      = (const float*)d_in[6];
    const float* wo      = (const float*)d_in[7];
    const float* bo      = (const float*)d_in[8];
    const float* ln1_g   = (const float*)d_in[9];
    const float* ln1_b   = (const float*)d_in[10];
    const float* w1      = (const float*)d_in[11];
    const float* b1      = (const float*)d_in[12];
    const float* w2      = (const float*)d_in[13];
    const float* b2      = (const float*)d_in[14];
    const float* lnf_g   = (const float*)d_in[15];
    const float* lnf_b   = (const float*)d_in[16];
    const float* lm_w    = (const float*)d_in[17];
    const float* lm_b    = (const float*)d_in[18];

    static int attr_set = 0;
    static cudaStream_t s_prep;
    static cudaEvent_t  e_fork, e_join;
    if (!attr_set) {
        cudaFuncSetAttribute(hgemm, cudaFuncAttributeMaxDynamicSharedMemorySize,
                             GEMM_SMEM);
        cudaFuncSetAttribute(flash_attn_tc, cudaFuncAttributeMaxDynamicSharedMemorySize,
                             FA_SMEM);
        cudaStreamCreateWithFlags(&s_prep, cudaStreamNonBlocking);
        cudaEventCreateWithFlags(&e_fork, cudaEventDisableTiming);
        cudaEventCreateWithFlags(&e_join, cudaEventDisableTiming);
        attr_set = 1;
    }

    float*  x;    cudaGetSymbolAddress((void**)&x,    g_x);
    __half* h16;  cudaGetSymbolAddress((void**)&h16,  g_h16);
    __half* qkv16;cudaGetSymbolAddress((void**)&qkv16,g_qkv16);
    __half* att16;cudaGetSymbolAddress((void**)&att16,g_att16);
    __half* ff16; cudaGetSymbolAddress((void**)&ff16, g_ff16);
    __half* wqkvp;cudaGetSymbolAddress((void**)&wqkvp,g_wqkv);
    __half* wop;  cudaGetSymbolAddress((void**)&wop,  g_wo);
    __half* w1p;  cudaGetSymbolAddress((void**)&w1p,  g_w1);
    __half* w2p;  cudaGetSymbolAddress((void**)&w2p,  g_w2);
    __half* lmwp; cudaGetSymbolAddress((void**)&lmwp, g_lmw);
    float*  glog; cudaGetSymbolAddress((void**)&glog, g_logits);
    float2* lossp;cudaGetSymbolAddress((void**)&lossp,g_losspart);

    const long long NLOG = (long long)ROWS * VOCAB;
    float* logits = ((long long)out_size >= NLOG) ? (float*)d_out : glog;

    dim3 tb(32, 8);
    dim3 agrid(SEQ_T / 64, N_HEADS, BATCH);
    const int PPG = (E3 * EMB + 255) / 256;

    // ---- fork: side stream does all weight prep not needed before proj L0 ----
    cudaEventRecord(e_fork, 0);
    cudaStreamWaitEvent(s_prep, e_fork, 0);
    for (int l = 0; l < NL_LAYERS; l++) {
        if (l > 0)
            prepack_qkv<<<PPG, 256, 0, s_prep>>>(wq, wk, wv, l);
        transpose_cvt<<<dim3(EMB / 32, EMB / 32), tb, 0, s_prep>>>(
            wo + (size_t)l * EMB * EMB, wop + (size_t)l * EMB * EMB, EMB, EMB);
        transpose_cvt<<<dim3(FF_DIM / 32, EMB / 32), tb, 0, s_prep>>>(
            w1 + (size_t)l * EMB * FF_DIM, w1p + (size_t)l * EMB * FF_DIM,
            EMB, FF_DIM);
        transpose_cvt<<<dim3(EMB / 32, FF_DIM / 32), tb, 0, s_prep>>>(
            w2 + (size_t)l * FF_DIM * EMB, w2p + (size_t)l * FF_DIM * EMB,
            FF_DIM, EMB);
    }
    transpose_cvt<<<dim3(VOCAB / 32, EMB / 32), tb, 0, s_prep>>>(
        lm_w, lmwp, EMB, VOCAB);
    cudaEventRecord(e_join, s_prep);

    // ---- main stream: layer-0 critical path overlaps with side prep ----
    prepack_qkv<<<PPG, 256>>>(wq, wk, wv, 0);
    embed_kernel<<<(ROWS * EMB / 4 + 255) / 256, 256>>>(ids, tok_emb, pos_emb);

    int joined = 0;
    for (int l = 0; l < NL_LAYERS; l++) {
        const float* g1  = ln1_g + l * EMB;
        const float* bt1 = ln1_b + l * EMB;

        ln_kernel<<<ROWS / 8, 256>>>(x, g1, bt1, h16);
        // qkv16 = f16(h @ Wqkv^T)
        run_gemm(h16, wqkvp + (size_t)l * E3 * EMB, nullptr, nullptr, nullptr,
                 qkv16, nullptr, ROWS, E3, EMB, 0);
        // tensor-core flash attention -> att16
        flash_attn_tc<<<agrid, 128, FA_SMEM>>>(qkv16, att16);
        // join side-stream prep before first use of transposed weights
        if (!joined) { cudaStreamWaitEvent(0, e_join, 0); joined = 1; }
        // x = x + att @ wo + bo
        run_gemm(att16, wop + (size_t)l * EMB * EMB, bo + l * EMB, x, x, nullptr,
                 nullptr, ROWS, EMB, EMB, 0);
        // h16 = f16(LN(x))
        ln_kernel<<<ROWS / 8, 256>>>(x, g1, bt1, h16);
        // ff16 = f16(relu(h @ w1 + b1))
        run_gemm(h16, w1p + (size_t)l * EMB * FF_DIM, b1 + l * FF_DIM, nullptr,
                 nullptr, ff16, nullptr, ROWS, FF_DIM, EMB, 1);
        // x = x + ff @ w2 + b2
        run_gemm(ff16, w2p + (size_t)l * FF_DIM * EMB, b2 + l * EMB, x, x, nullptr,
                 nullptr, ROWS, EMB, FF_DIM, 0);
    }

    // final LN + lm head (with fused loss partials)
    ln_kernel<<<ROWS / 8, 256>>>(x, lnf_g, lnf_b, h16);
    run_gemm(h16, lmwp, lm_b, nullptr, logits, nullptr, lossp,
             ROWS, VOCAB, EMB, 0);

    // loss from partials
    if (out_size == 1 || (long long)out_size > NLOG) {
        loss_rows_kernel<<<ROWS, 256>>>(logits, targets, lossp);
        float* loss_dst = (out_size == 1) ? (float*)d_out
                                          : ((float*)d_out + NLOG);
        loss_final_kernel<<<1, 256>>>(loss_dst);
    }
}